// round 2
// baseline (speedup 1.0000x reference)
#include <cuda_runtime.h>
#include <math.h>

// Problem constants
#define BB 32
#define TT 4096
#define DD 1024      // input dim == attn dim == values dim
#define HH 16
#define DHEAD 64     // per-head dim (dk == dv)
#define SCALE 8.0f   // sqrt(INPUT_DIM / H) = sqrt(64)

#define MKV (BB * TT) // 131072 rows for K/V projection

// Scratch (device globals; no allocations allowed)
__device__ float g_k[(size_t)MKV * DD];   // 512 MB
__device__ float g_v[(size_t)MKV * DD];   // 512 MB
__device__ float g_q[BB * DD];
__device__ float g_ctx[BB * DD];

// ---------------------------------------------------------------------------
// Small row projection: Y[b, :] = X[b, :] @ W + bias   (M = 32, N = K = 1024)
// grid = 32 blocks, 256 threads; each thread owns 4 output columns.
// ---------------------------------------------------------------------------
__global__ __launch_bounds__(256) void rowproj_kernel(
    const float* __restrict__ X, const float* __restrict__ W,
    const float* __restrict__ bias, float* __restrict__ Y) {
    __shared__ float xs[DD];
    const int b = blockIdx.x;
    const int tid = threadIdx.x;
    const float* xr = X + (size_t)b * DD;
    for (int i = tid; i < DD; i += 256) xs[i] = xr[i];
    __syncthreads();

    float acc0 = 0.f, acc1 = 0.f, acc2 = 0.f, acc3 = 0.f;
#pragma unroll 4
    for (int k = 0; k < DD; k++) {
        const float xv = xs[k];
        const float* wr = W + (size_t)k * DD;
        acc0 += xv * wr[tid];
        acc1 += xv * wr[tid + 256];
        acc2 += xv * wr[tid + 512];
        acc3 += xv * wr[tid + 768];
    }
    float* yr = Y + (size_t)b * DD;
    yr[tid]       = acc0 + bias[tid];
    yr[tid + 256] = acc1 + bias[tid + 256];
    yr[tid + 512] = acc2 + bias[tid + 512];
    yr[tid + 768] = acc3 + bias[tid + 768];
}

// ---------------------------------------------------------------------------
// Classic 128x128x8 fp32 SGEMM with bias: C[M,N] = A[M,K] @ W[K,N] + bias
// 256 threads, each computes an 8x8 micro-tile. M,N % 128 == 0, K % 8 == 0.
// ---------------------------------------------------------------------------
__global__ __launch_bounds__(256) void sgemm128_bias_kernel(
    const float* __restrict__ A, const float* __restrict__ W,
    const float* __restrict__ bias, float* __restrict__ C,
    int M, int N, int K) {
    __shared__ float As[8][128];
    __shared__ float Bs[8][128];

    const int tid = threadIdx.x;
    const int tx = tid & 15;   // 16 thread-cols
    const int ty = tid >> 4;   // 16 thread-rows
    const int m0 = blockIdx.y * 128;
    const int n0 = blockIdx.x * 128;

    const int aRow = tid >> 1;          // 0..127
    const int aCol = (tid & 1) * 4;     // 0 or 4
    const int bRow = tid >> 5;          // 0..7
    const int bCol = (tid & 31) * 4;    // 0..124

    const float* Ap = A + (size_t)(m0 + aRow) * K + aCol;
    const float* Wp = W + (size_t)bRow * N + n0 + bCol;

    float acc[8][8];
#pragma unroll
    for (int i = 0; i < 8; i++)
#pragma unroll
        for (int j = 0; j < 8; j++) acc[i][j] = 0.f;

    for (int k0 = 0; k0 < K; k0 += 8) {
        const float4 av = *(const float4*)(Ap + k0);
        const float4 bv = *(const float4*)(Wp + (size_t)k0 * N);
        As[aCol + 0][aRow] = av.x;
        As[aCol + 1][aRow] = av.y;
        As[aCol + 2][aRow] = av.z;
        As[aCol + 3][aRow] = av.w;
        *(float4*)&Bs[bRow][bCol] = bv;
        __syncthreads();

#pragma unroll
        for (int k = 0; k < 8; k++) {
            float ar[8], br[8];
            *(float4*)&ar[0] = *(const float4*)&As[k][ty * 8];
            *(float4*)&ar[4] = *(const float4*)&As[k][ty * 8 + 4];
            *(float4*)&br[0] = *(const float4*)&Bs[k][tx * 8];
            *(float4*)&br[4] = *(const float4*)&Bs[k][tx * 8 + 4];
#pragma unroll
            for (int i = 0; i < 8; i++)
#pragma unroll
                for (int j = 0; j < 8; j++) acc[i][j] += ar[i] * br[j];
        }
        __syncthreads();
    }

#pragma unroll
    for (int i = 0; i < 8; i++) {
        const int row = m0 + ty * 8 + i;
        float* cr = C + (size_t)row * N + n0 + tx * 8;
#pragma unroll
        for (int j = 0; j < 8; j += 4) {
            const int col = n0 + tx * 8 + j;
            float4 o;
            o.x = acc[i][j + 0] + bias[col + 0];
            o.y = acc[i][j + 1] + bias[col + 1];
            o.z = acc[i][j + 2] + bias[col + 2];
            o.w = acc[i][j + 3] + bias[col + 3];
            *(float4*)(cr + j) = o;
        }
    }
}

// ---------------------------------------------------------------------------
// Per-(b,h) scores + masked softmax.
// scores[b,h,t] = sum_d (q[b,h*64+d]/SCALE) * k[b,t,h*64+d]   (raw, pre-mask)
// attn = softmax over t of (mask ? score : -1e30)
// grid = (H, B), 256 threads, 16 t's per thread held in registers.
// ---------------------------------------------------------------------------
__global__ __launch_bounds__(256) void attn_softmax_kernel(
    const float* __restrict__ q, const float* __restrict__ kmat,
    const int* __restrict__ mask,
    float* __restrict__ scores_out, float* __restrict__ attn_out) {
    const int h = blockIdx.x;
    const int b = blockIdx.y;
    const int tid = threadIdx.x;

    __shared__ float qs[DHEAD];
    __shared__ float red[256];
    if (tid < DHEAD) qs[tid] = q[b * DD + h * DHEAD + tid] * (1.0f / SCALE);
    __syncthreads();

    const int* mrow = mask + (size_t)b * TT;
    const size_t bt0 = (size_t)b * TT;
    const size_t orow = ((size_t)(b * HH + h)) * TT;

    float sloc[16];
    float lmax = -3.0e38f;
#pragma unroll 1
    for (int it = 0; it < 16; it++) {
        const int t = tid + it * 256;
        const float4* kp = (const float4*)(kmat + (bt0 + t) * DD + h * DHEAD);
        float s = 0.f;
#pragma unroll
        for (int i = 0; i < 16; i++) {
            const float4 kv = kp[i];
            s += qs[4 * i + 0] * kv.x + qs[4 * i + 1] * kv.y +
                 qs[4 * i + 2] * kv.z + qs[4 * i + 3] * kv.w;
        }
        scores_out[orow + t] = s;
        const float ms = (mrow[t] > 0) ? s : -1e30f;
        sloc[it] = ms;
        lmax = fmaxf(lmax, ms);
    }

    red[tid] = lmax;
    __syncthreads();
    for (int st = 128; st > 0; st >>= 1) {
        if (tid < st) red[tid] = fmaxf(red[tid], red[tid + st]);
        __syncthreads();
    }
    const float mx = red[0];
    __syncthreads();

    float lsum = 0.f;
#pragma unroll
    for (int it = 0; it < 16; it++) {
        const float e = expf(sloc[it] - mx);
        sloc[it] = e;
        lsum += e;
    }
    red[tid] = lsum;
    __syncthreads();
    for (int st = 128; st > 0; st >>= 1) {
        if (tid < st) red[tid] += red[tid + st];
        __syncthreads();
    }
    const float inv = 1.0f / red[0];

#pragma unroll
    for (int it = 0; it < 16; it++) {
        const int t = tid + it * 256;
        attn_out[orow + t] = sloc[it] * inv;
    }
}

// ---------------------------------------------------------------------------
// ctx[b, h*64+d] = sum_t attn[b,h,t] * v[b,t,h*64+d]
// grid = (H, B), 256 threads = 4 t-groups x 64 d-lanes.
// ---------------------------------------------------------------------------
__global__ __launch_bounds__(256) void ctx_kernel(
    const float* __restrict__ attn, const float* __restrict__ vmat,
    float* __restrict__ ctx) {
    const int h = blockIdx.x;
    const int b = blockIdx.y;
    const int tid = threadIdx.x;
    const int d = tid & 63;
    const int grp = tid >> 6;

    const float* arow = attn + ((size_t)(b * HH + h)) * TT;
    const float* vbase = vmat + (size_t)b * TT * DD + h * DHEAD + d;

    float acc = 0.f;
#pragma unroll 4
    for (int t = grp; t < TT; t += 4) {
        acc += arow[t] * vbase[(size_t)t * DD];
    }

    __shared__ float red[256];
    red[tid] = acc;
    __syncthreads();
    if (grp == 0) {
        ctx[b * DD + h * DHEAD + d] =
            red[d] + red[64 + d] + red[128 + d] + red[192 + d];
    }
}

// ---------------------------------------------------------------------------
// Launch
// ---------------------------------------------------------------------------
extern "C" void kernel_launch(void* const* d_in, const int* in_sizes, int n_in,
                              void* d_out, int out_size) {
    const float* vector = (const float*)d_in[0];
    const float* matrix = (const float*)d_in[1];
    const int*   mask   = (const int*)d_in[2];
    const float* Wq = (const float*)d_in[3];
    const float* bq = (const float*)d_in[4];
    const float* Wk = (const float*)d_in[5];
    const float* bk = (const float*)d_in[6];
    const float* Wv = (const float*)d_in[7];
    const float* bv = (const float*)d_in[8];
    const float* Wo = (const float*)d_in[9];
    const float* bo = (const float*)d_in[10];

    float* out = (float*)d_out;
    float* out_final  = out;                              // [32, 1024]
    float* attn_out   = out + (size_t)BB * DD;            // [32, 16, 4096]
    float* scores_out = attn_out + (size_t)BB * HH * TT;  // [32, 16, 4096]

    float *pk, *pv, *pq, *pctx;
    cudaGetSymbolAddress((void**)&pk, g_k);
    cudaGetSymbolAddress((void**)&pv, g_v);
    cudaGetSymbolAddress((void**)&pq, g_q);
    cudaGetSymbolAddress((void**)&pctx, g_ctx);

    // q = vector @ Wq + bq
    rowproj_kernel<<<BB, 256>>>(vector, Wq, bq, pq);

    // k = matrix @ Wk + bk ; v = matrix @ Wv + bv  (the 549 GFLOP term)
    dim3 ggrid(DD / 128, MKV / 128);
    sgemm128_bias_kernel<<<ggrid, 256>>>(matrix, Wk, bk, pk, MKV, DD, DD);
    sgemm128_bias_kernel<<<ggrid, 256>>>(matrix, Wv, bv, pv, MKV, DD, DD);

    // scores + masked softmax
    dim3 agrid(HH, BB);
    attn_softmax_kernel<<<agrid, 256>>>(pq, pk, mask, scores_out, attn_out);

    // ctx = attn @ V
    ctx_kernel<<<agrid, 256>>>(attn_out, pv, pctx);

    // out = ctx @ Wo + bo
    rowproj_kernel<<<BB, 256>>>(pctx, Wo, bo, out_final);
}

// round 5
// speedup vs baseline: 2.7686x; 2.7686x over previous
#include <cuda_runtime.h>
#include <math.h>
#include <stdint.h>

// Problem constants
#define BB 32
#define TT 4096
#define DD 1024
#define HH 16
#define DHEAD 64
#define SCALE 8.0f
#define MKV (BB * TT)   // 131072 rows

// GEMM tiling (fused K|V projection: N_total = 2048)
#define NTOT 2048
#define GTM 128
#define GTN 256
#define GKC 32
#define NCHUNK (DD / GKC)      // 32
#define LDSS 36                // padded smem row stride (floats)

// Scratch (device globals; no allocations allowed)
__device__ float g_k[(size_t)MKV * DD];      // 512 MB
__device__ float g_v[(size_t)MKV * DD];      // 512 MB
__device__ float g_a[(size_t)MKV * DD];      // 512 MB (tf32-rounded matrix)
__device__ float g_wt[NTOT * DD];            // [Wk^T ; Wv^T], tf32-rounded
__device__ float g_bkv[NTOT];                // [bk ; bv]
__device__ float g_q[BB * DD];
__device__ float g_ctx[BB * DD];

// ---------------------------------------------------------------------------
// Helpers
// ---------------------------------------------------------------------------
__device__ __forceinline__ uint32_t smem_u32(const void* p) {
    uint32_t a;
    asm("{ .reg .u64 t; cvta.to.shared.u64 t, %1; cvt.u32.u64 %0, t; }"
        : "=r"(a) : "l"(p));
    return a;
}
__device__ __forceinline__ uint32_t f2tf32(float x) {
    uint32_t u;
    asm("cvt.rna.tf32.f32 %0, %1;" : "=r"(u) : "f"(x));
    return u;
}
__device__ __forceinline__ void cp_async16(uint32_t sdst, const void* gsrc) {
    asm volatile("cp.async.cg.shared.global [%0], [%1], 16;" :: "r"(sdst), "l"(gsrc));
}
#define CP_COMMIT() asm volatile("cp.async.commit_group;" ::: "memory")
#define CP_WAIT(n)  asm volatile("cp.async.wait_group %0;" :: "n"(n) : "memory")

__device__ __forceinline__ void mma_tf32(
    float* c, uint32_t a0, uint32_t a1, uint32_t a2, uint32_t a3,
    uint32_t b0, uint32_t b1) {
    asm volatile(
        "mma.sync.aligned.m16n8k8.row.col.f32.tf32.tf32.f32 "
        "{%0,%1,%2,%3}, {%4,%5,%6,%7}, {%8,%9}, {%0,%1,%2,%3};"
        : "+f"(c[0]), "+f"(c[1]), "+f"(c[2]), "+f"(c[3])
        : "r"(a0), "r"(a1), "r"(a2), "r"(a3), "r"(b0), "r"(b1));
}

// ---------------------------------------------------------------------------
// Prepass: round fp32 -> tf32 (rna), elementwise
// ---------------------------------------------------------------------------
__global__ __launch_bounds__(256) void round_tf32_kernel(
    const float4* __restrict__ src, float4* __restrict__ dst, size_t n4) {
    size_t i = (size_t)blockIdx.x * blockDim.x + threadIdx.x;
    size_t stride = (size_t)gridDim.x * blockDim.x;
    for (; i < n4; i += stride) {
        float4 v = src[i];
        float4 o;
        o.x = __uint_as_float(f2tf32(v.x));
        o.y = __uint_as_float(f2tf32(v.y));
        o.z = __uint_as_float(f2tf32(v.z));
        o.w = __uint_as_float(f2tf32(v.w));
        dst[i] = o;
    }
}

// Transpose + round 1024x1024 weights: Wt[n][k] = tf32(W[k][n])
__global__ __launch_bounds__(256) void transpose_round_kernel(
    const float* __restrict__ W, float* __restrict__ Wt) {
    __shared__ float tile[32][33];
    const int k0 = blockIdx.y * 32;
    const int n0 = blockIdx.x * 32;
    const int tx = threadIdx.x & 31;
    const int ty = threadIdx.x >> 5;  // 0..7
    for (int r = ty; r < 32; r += 8)
        tile[r][tx] = W[(size_t)(k0 + r) * DD + n0 + tx];
    __syncthreads();
    for (int r = ty; r < 32; r += 8)
        Wt[(size_t)(n0 + r) * DD + k0 + tx] =
            __uint_as_float(f2tf32(tile[tx][r]));
}

__global__ void concat_bias_kernel(const float* __restrict__ bk,
                                   const float* __restrict__ bv,
                                   float* __restrict__ bkv) {
    const int i = blockIdx.x * blockDim.x + threadIdx.x;
    if (i < DD) {
        bkv[i] = bk[i];
        bkv[i + DD] = bv[i];
    }
}

// ---------------------------------------------------------------------------
// Fused tf32 GEMM (mma.sync, Ampere-style): computes K and V projections.
// C[:, 0:1024] -> g_k ; C[:, 1024:2048] -> g_v
// A [M,1024] row-major (tf32-rounded), Wt [2048,1024] row-major (tf32).
// grid = (NTOT/GTN=8, MKV/GTM=1024), block = 256 (8 warps, 64x64 warp tiles)
// ---------------------------------------------------------------------------
__global__ __launch_bounds__(256, 1) void gemm_mma_kernel(
    const float* __restrict__ A, const float* __restrict__ Wt,
    const float* __restrict__ bias, float* __restrict__ Ck,
    float* __restrict__ Cv) {
    extern __shared__ float smemf[];
    const int A_ELEMS = GTM * LDSS;   // 4608
    const int B_ELEMS = GTN * LDSS;   // 9216

    const int tid = threadIdx.x;
    const int wid = tid >> 5;
    const int lid = tid & 31;
    const int g = lid >> 2;     // group id 0..7
    const int tig = lid & 3;    // thread-in-group 0..3
    const int m0 = blockIdx.y * GTM;
    const int n0 = blockIdx.x * GTN;

    const int wm0 = (wid & 1) * 64;   // warp m offset in tile
    const int wn0 = (wid >> 1) * 64;  // warp n offset in tile

    float* sA[2] = {smemf, smemf + A_ELEMS};
    float* sB[2] = {smemf + 2 * A_ELEMS, smemf + 2 * A_ELEMS + B_ELEMS};
    const uint32_t sAu[2] = {smem_u32(sA[0]), smem_u32(sA[1])};
    const uint32_t sBu[2] = {smem_u32(sB[0]), smem_u32(sB[1])};

    float acc[4][8][4];
#pragma unroll
    for (int i = 0; i < 4; i++)
#pragma unroll
        for (int j = 0; j < 8; j++)
#pragma unroll
            for (int q = 0; q < 4; q++) acc[i][j][q] = 0.f;

    // per-chunk load: A 128x32 floats, B 256x32 floats, 16B units
    auto load_chunk = [&](int c, int s) {
        const int cf = c * GKC;  // float offset in K
#pragma unroll
        for (int i = 0; i < 4; i++) {  // A: 1024 units / 256 threads
            const int u = tid + i * 256;
            const int r = u >> 3, cp = (u & 7) * 4;
            cp_async16(sAu[s] + (uint32_t)(r * LDSS + cp) * 4,
                       A + ((size_t)(m0 + r)) * DD + cf + cp);
        }
#pragma unroll
        for (int i = 0; i < 8; i++) {  // B: 2048 units / 256 threads
            const int u = tid + i * 256;
            const int r = u >> 3, cp = (u & 7) * 4;
            cp_async16(sBu[s] + (uint32_t)(r * LDSS + cp) * 4,
                       Wt + ((size_t)(n0 + r)) * DD + cf + cp);
        }
        CP_COMMIT();
    };

    load_chunk(0, 0);

    for (int c = 0; c < NCHUNK; c++) {
        const int s = c & 1;
        if (c + 1 < NCHUNK) {
            load_chunk(c + 1, s ^ 1);
            CP_WAIT(1);
        } else {
            CP_WAIT(0);
        }
        __syncthreads();

        const float* As = sA[s];
        const float* Bs = sB[s];
#pragma unroll
        for (int ks = 0; ks < 4; ks++) {
            const int kb = ks * 8;
            // A fragments: 4 m-blocks of 16 rows
            uint32_t af[4][4];
#pragma unroll
            for (int im = 0; im < 4; im++) {
                const int rb = wm0 + im * 16;
                af[im][0] = __float_as_uint(As[(rb + g) * LDSS + kb + tig]);
                af[im][1] = __float_as_uint(As[(rb + g + 8) * LDSS + kb + tig]);
                af[im][2] = __float_as_uint(As[(rb + g) * LDSS + kb + tig + 4]);
                af[im][3] = __float_as_uint(As[(rb + g + 8) * LDSS + kb + tig + 4]);
            }
#pragma unroll
            for (int jn = 0; jn < 8; jn++) {
                const int nb = wn0 + jn * 8;
                const uint32_t b0 = __float_as_uint(Bs[(nb + g) * LDSS + kb + tig]);
                const uint32_t b1 = __float_as_uint(Bs[(nb + g) * LDSS + kb + tig + 4]);
#pragma unroll
                for (int im = 0; im < 4; im++) {
                    mma_tf32(acc[im][jn], af[im][0], af[im][1], af[im][2],
                             af[im][3], b0, b1);
                }
            }
        }
        __syncthreads();
    }

    // Epilogue: route columns to K or V output
    float* outp = (n0 < DD) ? Ck : Cv;
    const int colbase = n0 & (DD - 1);
#pragma unroll
    for (int im = 0; im < 4; im++) {
        const int row = m0 + wm0 + im * 16 + g;
#pragma unroll
        for (int jn = 0; jn < 8; jn++) {
            const int cl = wn0 + jn * 8 + 2 * tig;
            const float bx = bias[n0 + cl];
            const float by = bias[n0 + cl + 1];
            float2 v0 = {acc[im][jn][0] + bx, acc[im][jn][1] + by};
            float2 v1 = {acc[im][jn][2] + bx, acc[im][jn][3] + by};
            *(float2*)(outp + (size_t)row * DD + colbase + cl) = v0;
            *(float2*)(outp + (size_t)(row + 8) * DD + colbase + cl) = v1;
        }
    }
}

// ---------------------------------------------------------------------------
// Small row projection: Y[b, :] = X[b, :] @ W + bias (M=32, N=K=1024)
// ---------------------------------------------------------------------------
__global__ __launch_bounds__(256) void rowproj_kernel(
    const float* __restrict__ X, const float* __restrict__ W,
    const float* __restrict__ bias, float* __restrict__ Y) {
    __shared__ float xs[DD];
    const int b = blockIdx.x;
    const int tid = threadIdx.x;
    const float* xr = X + (size_t)b * DD;
    for (int i = tid; i < DD; i += 256) xs[i] = xr[i];
    __syncthreads();
    float a0 = 0.f, a1 = 0.f, a2 = 0.f, a3 = 0.f;
#pragma unroll 4
    for (int k = 0; k < DD; k++) {
        const float xv = xs[k];
        const float* wr = W + (size_t)k * DD;
        a0 += xv * wr[tid];
        a1 += xv * wr[tid + 256];
        a2 += xv * wr[tid + 512];
        a3 += xv * wr[tid + 768];
    }
    float* yr = Y + (size_t)b * DD;
    yr[tid]       = a0 + bias[tid];
    yr[tid + 256] = a1 + bias[tid + 256];
    yr[tid + 512] = a2 + bias[tid + 512];
    yr[tid + 768] = a3 + bias[tid + 768];
}

// ---------------------------------------------------------------------------
// Per-(b,h) scores + masked softmax
// ---------------------------------------------------------------------------
__global__ __launch_bounds__(256) void attn_softmax_kernel(
    const float* __restrict__ q, const float* __restrict__ kmat,
    const int* __restrict__ mask,
    float* __restrict__ scores_out, float* __restrict__ attn_out) {
    const int h = blockIdx.x;
    const int b = blockIdx.y;
    const int tid = threadIdx.x;

    __shared__ float qs[DHEAD];
    __shared__ float red[256];
    if (tid < DHEAD) qs[tid] = q[b * DD + h * DHEAD + tid] * (1.0f / SCALE);
    __syncthreads();

    const int* mrow = mask + (size_t)b * TT;
    const size_t bt0 = (size_t)b * TT;
    const size_t orow = ((size_t)(b * HH + h)) * TT;

    float sloc[16];
    float lmax = -3.0e38f;
#pragma unroll 1
    for (int it = 0; it < 16; it++) {
        const int t = tid + it * 256;
        const float4* kp = (const float4*)(kmat + (bt0 + t) * DD + h * DHEAD);
        float s = 0.f;
#pragma unroll
        for (int i = 0; i < 16; i++) {
            const float4 kv = kp[i];
            s += qs[4 * i + 0] * kv.x + qs[4 * i + 1] * kv.y +
                 qs[4 * i + 2] * kv.z + qs[4 * i + 3] * kv.w;
        }
        scores_out[orow + t] = s;
        const float ms = (mrow[t] > 0) ? s : -1e30f;
        sloc[it] = ms;
        lmax = fmaxf(lmax, ms);
    }

    red[tid] = lmax;
    __syncthreads();
    for (int st = 128; st > 0; st >>= 1) {
        if (tid < st) red[tid] = fmaxf(red[tid], red[tid + st]);
        __syncthreads();
    }
    const float mx = red[0];
    __syncthreads();

    float lsum = 0.f;
#pragma unroll
    for (int it = 0; it < 16; it++) {
        const float e = expf(sloc[it] - mx);
        sloc[it] = e;
        lsum += e;
    }
    red[tid] = lsum;
    __syncthreads();
    for (int st = 128; st > 0; st >>= 1) {
        if (tid < st) red[tid] += red[tid + st];
        __syncthreads();
    }
    const float inv = 1.0f / red[0];
#pragma unroll
    for (int it = 0; it < 16; it++) {
        const int t = tid + it * 256;
        attn_out[orow + t] = sloc[it] * inv;
    }
}

// ---------------------------------------------------------------------------
// ctx[b, h*64+d] = sum_t attn[b,h,t] * v[b,t,h*64+d]
// ---------------------------------------------------------------------------
__global__ __launch_bounds__(256) void ctx_kernel(
    const float* __restrict__ attn, const float* __restrict__ vmat,
    float* __restrict__ ctx) {
    const int h = blockIdx.x;
    const int b = blockIdx.y;
    const int tid = threadIdx.x;
    const int d = tid & 63;
    const int grp = tid >> 6;

    const float* arow = attn + ((size_t)(b * HH + h)) * TT;
    const float* vbase = vmat + (size_t)b * TT * DD + h * DHEAD + d;

    float acc = 0.f;
#pragma unroll 4
    for (int t = grp; t < TT; t += 4) acc += arow[t] * vbase[(size_t)t * DD];

    __shared__ float red[256];
    red[tid] = acc;
    __syncthreads();
    if (grp == 0) {
        ctx[b * DD + h * DHEAD + d] =
            red[d] + red[64 + d] + red[128 + d] + red[192 + d];
    }
}

// ---------------------------------------------------------------------------
// Launch
// ---------------------------------------------------------------------------
extern "C" void kernel_launch(void* const* d_in, const int* in_sizes, int n_in,
                              void* d_out, int out_size) {
    const float* vector = (const float*)d_in[0];
    const float* matrix = (const float*)d_in[1];
    const int*   mask   = (const int*)d_in[2];
    const float* Wq = (const float*)d_in[3];
    const float* bq = (const float*)d_in[4];
    const float* Wk = (const float*)d_in[5];
    const float* bk = (const float*)d_in[6];
    const float* Wv = (const float*)d_in[7];
    const float* bv = (const float*)d_in[8];
    const float* Wo = (const float*)d_in[9];
    const float* bo = (const float*)d_in[10];

    float* out = (float*)d_out;
    float* out_final  = out;
    float* attn_out   = out + (size_t)BB * DD;
    float* scores_out = attn_out + (size_t)BB * HH * TT;

    float *pk, *pv, *pa, *pwt, *pbkv, *pq, *pctx;
    cudaGetSymbolAddress((void**)&pk, g_k);
    cudaGetSymbolAddress((void**)&pv, g_v);
    cudaGetSymbolAddress((void**)&pa, g_a);
    cudaGetSymbolAddress((void**)&pwt, g_wt);
    cudaGetSymbolAddress((void**)&pbkv, g_bkv);
    cudaGetSymbolAddress((void**)&pq, g_q);
    cudaGetSymbolAddress((void**)&pctx, g_ctx);

    const int GEMM_SMEM = (2 * GTM * LDSS + 2 * GTN * LDSS) * 4;  // 110592 B
    cudaFuncSetAttribute(gemm_mma_kernel,
                         cudaFuncAttributeMaxDynamicSharedMemorySize,
                         GEMM_SMEM);

    // Prepass: round matrix to tf32; transpose+round weights; concat bias
    round_tf32_kernel<<<2048, 256>>>((const float4*)matrix, (float4*)pa,
                                     (size_t)MKV * DD / 4);
    dim3 tgrid(DD / 32, DD / 32);
    transpose_round_kernel<<<tgrid, 256>>>(Wk, pwt);
    transpose_round_kernel<<<tgrid, 256>>>(Wv, pwt + (size_t)DD * DD);
    concat_bias_kernel<<<4, 256>>>(bk, bv, pbkv);

    // q = vector @ Wq + bq (fp32 SIMT — tiny)
    rowproj_kernel<<<BB, 256>>>(vector, Wq, bq, pq);

    // Fused K|V projection on tensor cores (tf32 mma.sync)
    dim3 ggrid(NTOT / GTN, MKV / GTM);
    gemm_mma_kernel<<<ggrid, 256, GEMM_SMEM>>>(pa, pwt, pbkv, pk, pv);

    // scores + masked softmax
    dim3 agrid(HH, BB);
    attn_softmax_kernel<<<agrid, 256>>>(pq, pk, mask, scores_out, attn_out);

    // ctx = attn @ V
    ctx_kernel<<<agrid, 256>>>(attn_out, pv, pctx);

    // out = ctx @ Wo + bo
    rowproj_kernel<<<BB, 256>>>(pctx, Wo, bo, out_final);
}

// round 6
// speedup vs baseline: 9.9916x; 3.6089x over previous
#include <cuda_runtime.h>
#include <math.h>
#include <stdint.h>

// Problem constants
#define BB 32
#define TT 4096
#define DD 1024
#define HH 16
#define DHEAD 64
#define MKV (BB * TT)

// Scratch (device globals; no allocations allowed)
__device__ float g_q[BB * DD];                         // q = vector@Wq + bq
__device__ float g_wqt[BB * DD * HH];                  // wq~[b][i][h] (2 MB)
__device__ float g_sb[BB * HH];                        // q^ . bk per (b,h)
__device__ float g_rpart[BB * 8 * HH * DD];            // partial r (16 MB)
__device__ float g_r[BB * HH * DD];                    // r[b][h][i] (2 MB)
__device__ float g_ctx[BB * DD];

// ---------------------------------------------------------------------------
// Row projection: Y[b,:] = X[b,:] @ W + bias   (M=32, N=K=1024)
// ---------------------------------------------------------------------------
__global__ __launch_bounds__(256) void rowproj_kernel(
    const float* __restrict__ X, const float* __restrict__ W,
    const float* __restrict__ bias, float* __restrict__ Y) {
    __shared__ float xs[DD];
    const int b = blockIdx.x;
    const int tid = threadIdx.x;
    const float* xr = X + (size_t)b * DD;
    for (int i = tid; i < DD; i += 256) xs[i] = xr[i];
    __syncthreads();
    float a0 = 0.f, a1 = 0.f, a2 = 0.f, a3 = 0.f;
#pragma unroll 4
    for (int k = 0; k < DD; k++) {
        const float xv = xs[k];
        const float* wr = W + (size_t)k * DD;
        a0 += xv * wr[tid];
        a1 += xv * wr[tid + 256];
        a2 += xv * wr[tid + 512];
        a3 += xv * wr[tid + 768];
    }
    float* yr = Y + (size_t)b * DD;
    yr[tid]       = a0 + bias[tid];
    yr[tid + 256] = a1 + bias[tid + 256];
    yr[tid + 512] = a2 + bias[tid + 512];
    yr[tid + 768] = a3 + bias[tid + 768];
}

// ---------------------------------------------------------------------------
// wq~[b][i][h] = (1/8) * sum_d Wk[i][h*64+d] * q[b][h*64+d]
// grid = (4 i-tiles, 32 b), block = 256 (thread = one i row)
// Processes one head (64 d's) per chunk; Wk tile staged in smem.
// ---------------------------------------------------------------------------
#define WQT_SMEM ((256 * 65 + 64) * 4)
__global__ __launch_bounds__(256) void wqt_kernel(
    const float* __restrict__ Wk, const float* __restrict__ q,
    float* __restrict__ wqt) {
    extern __shared__ float sm[];
    float* wk_s = sm;               // [256][65]
    float* q_s  = sm + 256 * 65;    // [64]
    const int tid = threadIdx.x;
    const int i0 = blockIdx.x * 256;
    const int b = blockIdx.y;

    float acc[HH];
#pragma unroll 1
    for (int h = 0; h < HH; h++) {
        __syncthreads();
        if (tid < 16)
            ((float4*)q_s)[tid] =
                ((const float4*)(q + (size_t)b * DD + h * DHEAD))[tid];
        // Stage Wk[i0..i0+255][h*64 .. h*64+63]
#pragma unroll
        for (int j = 0; j < 16; j++) {
            const int u = tid + j * 256;
            const int row = u >> 4, i4 = u & 15;
            float4 v = ((const float4*)Wk)[(size_t)(i0 + row) * 256 + h * 16 + i4];
            float* d = wk_s + row * 65 + i4 * 4;
            d[0] = v.x; d[1] = v.y; d[2] = v.z; d[3] = v.w;
        }
        __syncthreads();
        float s = 0.f;
        const float* wr = wk_s + tid * 65;
#pragma unroll 8
        for (int dd = 0; dd < 64; dd++) s += wr[dd] * q_s[dd];
        acc[h] = s * 0.125f;
    }
    float* o = wqt + ((size_t)b * DD + i0 + tid) * HH;
#pragma unroll
    for (int h = 0; h < HH; h++) o[h] = acc[h];
}

// ---------------------------------------------------------------------------
// sb[b][h] = (1/8) * sum_d bk[h*64+d] * q[b][h*64+d]
// grid = 32 (b), block = 512 (warp = head)
// ---------------------------------------------------------------------------
__global__ __launch_bounds__(512) void sb_kernel(
    const float* __restrict__ bk, const float* __restrict__ q,
    float* __restrict__ sb) {
    const int b = blockIdx.x;
    const int h = threadIdx.x >> 5;
    const int lane = threadIdx.x & 31;
    const int hd = h * DHEAD + lane * 2;
    float s = bk[hd] * q[b * DD + hd] + bk[hd + 1] * q[b * DD + hd + 1];
#pragma unroll
    for (int o = 16; o > 0; o >>= 1)
        s += __shfl_down_sync(0xFFFFFFFF, s, o);
    if (lane == 0) sb[b * HH + h] = s * 0.125f;
}

// ---------------------------------------------------------------------------
// scores[b][h][t] = matrix[b][t][:] . wq~[b][:][h]  + sb[b][h]
// grid = (16 t-tiles of 256, 32 b), block = 256 (thread = one t)
// ---------------------------------------------------------------------------
#define SC_WQ_FLOATS (DD * HH)             // 16384
#define SC_M_FLOATS  (256 * 65)            // 16640
#define SC_SMEM ((SC_WQ_FLOATS + SC_M_FLOATS) * 4)   // 132096 B
__global__ __launch_bounds__(256) void scores_kernel(
    const float* __restrict__ matrix, const float* __restrict__ wqt,
    const float* __restrict__ sb, float* __restrict__ scores_out) {
    extern __shared__ float sm[];
    float* wq_s = sm;                   // [1024][16]
    float* m_s  = sm + SC_WQ_FLOATS;    // [256][65]
    const int tid = threadIdx.x;
    const int t0 = blockIdx.x * 256;
    const int b = blockIdx.y;

    // load wq~ for this b (16384 floats)
    {
        const float4* src = (const float4*)(wqt + (size_t)b * DD * HH);
        float4* dst = (float4*)wq_s;
#pragma unroll
        for (int j = 0; j < 16; j++) dst[tid + j * 256] = src[tid + j * 256];
    }

    float acc[HH];
#pragma unroll
    for (int h = 0; h < HH; h++) acc[h] = 0.f;

#pragma unroll 1
    for (int ic = 0; ic < 16; ic++) {
        __syncthreads();
        // stage matrix[b][t0..t0+255][ic*64 .. +63]
#pragma unroll
        for (int j = 0; j < 16; j++) {
            const int u = tid + j * 256;
            const int t = u >> 4, i4 = u & 15;
            float4 v = ((const float4*)matrix)[
                (size_t)(b * TT + t0 + t) * 256 + ic * 16 + i4];
            float* d = m_s + t * 65 + i4 * 4;
            d[0] = v.x; d[1] = v.y; d[2] = v.z; d[3] = v.w;
        }
        __syncthreads();
        const float* mr = m_s + tid * 65;
        const float* wc = wq_s + ic * 64 * HH;
#pragma unroll 8
        for (int dd = 0; dd < 64; dd++) {
            const float mv = mr[dd];
            const float4* w4 = (const float4*)(wc + dd * HH);
            float4 w0 = w4[0], w1 = w4[1], w2 = w4[2], w3 = w4[3];
            acc[0]  += mv * w0.x; acc[1]  += mv * w0.y;
            acc[2]  += mv * w0.z; acc[3]  += mv * w0.w;
            acc[4]  += mv * w1.x; acc[5]  += mv * w1.y;
            acc[6]  += mv * w1.z; acc[7]  += mv * w1.w;
            acc[8]  += mv * w2.x; acc[9]  += mv * w2.y;
            acc[10] += mv * w2.z; acc[11] += mv * w2.w;
            acc[12] += mv * w3.x; acc[13] += mv * w3.y;
            acc[14] += mv * w3.z; acc[15] += mv * w3.w;
        }
    }
#pragma unroll
    for (int h = 0; h < HH; h++)
        scores_out[((size_t)(b * HH + h)) * TT + t0 + tid] =
            acc[h] + sb[b * HH + h];
}

// ---------------------------------------------------------------------------
// Masked softmax over t: attn[b][h][:] from scores + mask
// grid = (16 h, 32 b), block = 256, 16 t per thread
// ---------------------------------------------------------------------------
__global__ __launch_bounds__(256) void softmax_kernel(
    const float* __restrict__ scores, const int* __restrict__ mask,
    float* __restrict__ attn_out) {
    const int h = blockIdx.x;
    const int b = blockIdx.y;
    const int tid = threadIdx.x;
    __shared__ float red[256];

    const int* mrow = mask + (size_t)b * TT;
    const size_t orow = ((size_t)(b * HH + h)) * TT;

    float sloc[16];
    float lmax = -3.0e38f;
#pragma unroll
    for (int it = 0; it < 16; it++) {
        const int t = tid + it * 256;
        const float s = scores[orow + t];
        const float ms = (mrow[t] > 0) ? s : -1e30f;
        sloc[it] = ms;
        lmax = fmaxf(lmax, ms);
    }
    red[tid] = lmax;
    __syncthreads();
    for (int st = 128; st > 0; st >>= 1) {
        if (tid < st) red[tid] = fmaxf(red[tid], red[tid + st]);
        __syncthreads();
    }
    const float mx = red[0];
    __syncthreads();

    float lsum = 0.f;
#pragma unroll
    for (int it = 0; it < 16; it++) {
        const float e = expf(sloc[it] - mx);
        sloc[it] = e;
        lsum += e;
    }
    red[tid] = lsum;
    __syncthreads();
    for (int st = 128; st > 0; st >>= 1) {
        if (tid < st) red[tid] += red[tid + st];
        __syncthreads();
    }
    const float inv = 1.0f / red[0];
#pragma unroll
    for (int it = 0; it < 16; it++)
        attn_out[orow + tid + it * 256] = sloc[it] * inv;
}

// ---------------------------------------------------------------------------
// Partial r: rpart[b*8+cb][h][i] = sum_{t in chunk} attn[b][h][t]*matrix[b][t][i]
// grid = (8 t-chunks of 512, 32 b), block = 256 (thread = 4 i columns, float4)
// ---------------------------------------------------------------------------
__global__ __launch_bounds__(256) void rpart_kernel(
    const float* __restrict__ attn, const float* __restrict__ matrix,
    float* __restrict__ rpart) {
    __shared__ float attn_s[HH * 512];
    const int tid = threadIdx.x;
    const int cb = blockIdx.x;
    const int b = blockIdx.y;
    const int t0 = cb * 512;

#pragma unroll
    for (int j = 0; j < 32; j++) {
        const int u = tid + j * 256;
        const int h = u >> 9, t = u & 511;
        attn_s[u] = attn[((size_t)(b * HH + h)) * TT + t0 + t];
    }
    __syncthreads();

    float4 acc[HH];
#pragma unroll
    for (int h = 0; h < HH; h++) acc[h] = make_float4(0.f, 0.f, 0.f, 0.f);

#pragma unroll 4
    for (int t = 0; t < 512; t++) {
        const float4 m = ((const float4*)matrix)[
            (size_t)(b * TT + t0 + t) * 256 + tid];
#pragma unroll
        for (int h = 0; h < HH; h++) {
            const float a = attn_s[h * 512 + t];
            acc[h].x += a * m.x;
            acc[h].y += a * m.y;
            acc[h].z += a * m.z;
            acc[h].w += a * m.w;
        }
    }
#pragma unroll
    for (int h = 0; h < HH; h++)
        ((float4*)rpart)[((size_t)(b * 8 + cb) * HH + h) * 256 + tid] = acc[h];
}

// ---------------------------------------------------------------------------
// Reduce partials: r[b][h][i] = sum_cb rpart[b*8+cb][h][i]
// grid = 512, block = 256 (float4 per thread)
// ---------------------------------------------------------------------------
__global__ __launch_bounds__(256) void rreduce_kernel(
    const float* __restrict__ rpart, float* __restrict__ r) {
    const int e4 = blockIdx.x * 256 + threadIdx.x;  // 0..131071
    const int b = e4 >> 12;
    const int off = e4 & 4095;
    float4 acc = make_float4(0.f, 0.f, 0.f, 0.f);
#pragma unroll
    for (int c = 0; c < 8; c++) {
        const float4 v = ((const float4*)rpart)[(size_t)(b * 8 + c) * 4096 + off];
        acc.x += v.x; acc.y += v.y; acc.z += v.z; acc.w += v.w;
    }
    ((float4*)r)[(size_t)b * 4096 + off] = acc;
}

// ---------------------------------------------------------------------------
// ctx[b][hd] = sum_i r[b][hd>>6][i] * Wv[i][hd] + bv[hd]
// grid = (4 hd-tiles, 32 b), block = 256
// ---------------------------------------------------------------------------
__global__ __launch_bounds__(256) void ctx_kernel(
    const float* __restrict__ r, const float* __restrict__ Wv,
    const float* __restrict__ bv, float* __restrict__ ctx) {
    __shared__ float r_s[4 * DD];   // 4 heads worth
    const int tid = threadIdx.x;
    const int hd = blockIdx.x * 256 + tid;
    const int b = blockIdx.y;
    const int h0 = (blockIdx.x * 256) >> 6;   // first head in this tile

    {
        const float4* src = (const float4*)(r + ((size_t)b * HH + h0) * DD);
        float4* dst = (float4*)r_s;
#pragma unroll
        for (int j = 0; j < 4; j++) dst[tid + j * 256] = src[tid + j * 256];
    }
    __syncthreads();

    const float* rr = r_s + ((hd >> 6) - h0) * DD;
    float acc = 0.f;
#pragma unroll 4
    for (int i = 0; i < DD; i++) acc += rr[i] * Wv[(size_t)i * DD + hd];
    ctx[(size_t)b * DD + hd] = acc + bv[hd];
}

// ---------------------------------------------------------------------------
// Launch
// ---------------------------------------------------------------------------
extern "C" void kernel_launch(void* const* d_in, const int* in_sizes, int n_in,
                              void* d_out, int out_size) {
    const float* vector = (const float*)d_in[0];
    const float* matrix = (const float*)d_in[1];
    const int*   mask   = (const int*)d_in[2];
    const float* Wq = (const float*)d_in[3];
    const float* bq = (const float*)d_in[4];
    const float* Wk = (const float*)d_in[5];
    const float* bk = (const float*)d_in[6];
    const float* Wv = (const float*)d_in[7];
    const float* bv = (const float*)d_in[8];
    const float* Wo = (const float*)d_in[9];
    const float* bo = (const float*)d_in[10];

    float* out = (float*)d_out;
    float* out_final  = out;                              // [32, 1024]
    float* attn_out   = out + (size_t)BB * DD;            // [32, 16, 4096]
    float* scores_out = attn_out + (size_t)BB * HH * TT;  // [32, 16, 4096]

    float *pq, *pwqt, *psb, *prp, *pr, *pctx;
    cudaGetSymbolAddress((void**)&pq, g_q);
    cudaGetSymbolAddress((void**)&pwqt, g_wqt);
    cudaGetSymbolAddress((void**)&psb, g_sb);
    cudaGetSymbolAddress((void**)&prp, g_rpart);
    cudaGetSymbolAddress((void**)&pr, g_r);
    cudaGetSymbolAddress((void**)&pctx, g_ctx);

    cudaFuncSetAttribute(scores_kernel,
                         cudaFuncAttributeMaxDynamicSharedMemorySize, SC_SMEM);
    cudaFuncSetAttribute(wqt_kernel,
                         cudaFuncAttributeMaxDynamicSharedMemorySize, WQT_SMEM);

    // q = vector @ Wq + bq
    rowproj_kernel<<<BB, 256>>>(vector, Wq, bq, pq);

    // wq~ = Wk . q^  and  sb = q^ . bk
    dim3 wgrid(4, BB);
    wqt_kernel<<<wgrid, 256, WQT_SMEM>>>(Wk, pq, pwqt);
    sb_kernel<<<BB, 512>>>(bk, pq, psb);

    // scores = matrix @ wq~ + sb
    dim3 sgrid(16, BB);
    scores_kernel<<<sgrid, 256, SC_SMEM>>>(matrix, pwqt, psb, scores_out);

    // attn = masked softmax(scores)
    dim3 smgrid(HH, BB);
    softmax_kernel<<<smgrid, 256>>>(scores_out, mask, attn_out);

    // r = attn @ matrix (partials over t-chunks, then reduce)
    dim3 rgrid(8, BB);
    rpart_kernel<<<rgrid, 256>>>(attn_out, matrix, prp);
    rreduce_kernel<<<512, 256>>>(prp, pr);

    // ctx = r @ Wv + bv
    dim3 cgrid(4, BB);
    ctx_kernel<<<cgrid, 256>>>(pr, Wv, bv, pctx);

    // out = ctx @ Wo + bo
    rowproj_kernel<<<BB, 256>>>(pctx, Wo, bo, out_final);
}

// round 7
// speedup vs baseline: 20.2034x; 2.0220x over previous
#include <cuda_runtime.h>
#include <math.h>
#include <stdint.h>

#define BB 32
#define TT 4096
#define DD 1024
#define HH 16
#define DHEAD 64

// Scratch (device globals; no allocations)
__device__ float g_q[BB * DD];
__device__ float g_wqt[BB * HH * DD];   // wq~[b][h][i], tf32-rounded, incl /8
__device__ float g_sb[BB * HH];
__device__ float g_r[BB * HH * DD];     // r[b][h][i]
__device__ float g_ctx[BB * DD];
__device__ float g_pp[BB * 4 * DD];     // rowproj partials

// ---------------------------------------------------------------------------
__device__ __forceinline__ uint32_t f2tf32(float x) {
    uint32_t u;
    asm("cvt.rna.tf32.f32 %0, %1;" : "=r"(u) : "f"(x));
    return u;
}
__device__ __forceinline__ void cp_async16(uint32_t sdst, const void* gsrc) {
    asm volatile("cp.async.cg.shared.global [%0], [%1], 16;" :: "r"(sdst), "l"(gsrc));
}
#define CP_COMMIT() asm volatile("cp.async.commit_group;" ::: "memory")
#define CP_WAIT0()  asm volatile("cp.async.wait_group 0;" ::: "memory")
__device__ __forceinline__ uint32_t smem_u32(const void* p) {
    uint32_t a;
    asm("{ .reg .u64 t; cvta.to.shared.u64 t, %1; cvt.u32.u64 %0, t; }"
        : "=r"(a) : "l"(p));
    return a;
}
__device__ __forceinline__ void mma_tf32(
    float* c, uint32_t a0, uint32_t a1, uint32_t a2, uint32_t a3,
    uint32_t b0, uint32_t b1) {
    asm volatile(
        "mma.sync.aligned.m16n8k8.row.col.f32.tf32.tf32.f32 "
        "{%0,%1,%2,%3}, {%4,%5,%6,%7}, {%8,%9}, {%0,%1,%2,%3};"
        : "+f"(c[0]), "+f"(c[1]), "+f"(c[2]), "+f"(c[3])
        : "r"(a0), "r"(a1), "r"(a2), "r"(a3), "r"(b0), "r"(b1));
}
__device__ __forceinline__ float4 cvt4(float4 v) {
    float4 o;
    o.x = __uint_as_float(f2tf32(v.x));
    o.y = __uint_as_float(f2tf32(v.y));
    o.z = __uint_as_float(f2tf32(v.z));
    o.w = __uint_as_float(f2tf32(v.w));
    return o;
}

// ---------------------------------------------------------------------------
// Split row projection: partials over k-slices of 256, then reduce.
// rp_part: grid (4, 32); rp_reduce: grid 32.
// ---------------------------------------------------------------------------
__global__ __launch_bounds__(256) void rp_part_kernel(
    const float* __restrict__ X, const float* __restrict__ W,
    float* __restrict__ pp) {
    __shared__ float xs[256];
    const int s = blockIdx.x;
    const int b = blockIdx.y;
    const int tid = threadIdx.x;
    xs[tid] = X[(size_t)b * DD + s * 256 + tid];
    __syncthreads();
    float a0 = 0.f, a1 = 0.f, a2 = 0.f, a3 = 0.f;
#pragma unroll 8
    for (int k = 0; k < 256; k++) {
        const float xv = xs[k];
        const float* wr = W + (size_t)(s * 256 + k) * DD;
        a0 += xv * wr[tid];
        a1 += xv * wr[tid + 256];
        a2 += xv * wr[tid + 512];
        a3 += xv * wr[tid + 768];
    }
    float* o = pp + (size_t)(b * 4 + s) * DD;
    o[tid] = a0; o[tid + 256] = a1; o[tid + 512] = a2; o[tid + 768] = a3;
}

__global__ __launch_bounds__(256) void rp_reduce_kernel(
    const float* __restrict__ pp, const float* __restrict__ bias,
    float* __restrict__ Y) {
    const int b = blockIdx.x;
    const int tid = threadIdx.x;
#pragma unroll
    for (int j = 0; j < 4; j++) {
        const int c = tid + j * 256;
        float s = bias[c];
#pragma unroll
        for (int sl = 0; sl < 4; sl++) s += pp[(size_t)(b * 4 + sl) * DD + c];
        Y[(size_t)b * DD + c] = s;
    }
}

// ---------------------------------------------------------------------------
// wq~[b][h][i] = tf32( (1/8) * sum_d Wk[i][h*64+d] * q[b][h*64+d] )
// grid = (4 i-tiles, 32 b), block = 256
// ---------------------------------------------------------------------------
#define WQT_SMEM ((256 * 65 + 64) * 4)
__global__ __launch_bounds__(256) void wqt_kernel(
    const float* __restrict__ Wk, const float* __restrict__ q,
    float* __restrict__ wqt) {
    extern __shared__ float sm[];
    float* wk_s = sm;
    float* q_s  = sm + 256 * 65;
    const int tid = threadIdx.x;
    const int i0 = blockIdx.x * 256;
    const int b = blockIdx.y;

    float acc[HH];
#pragma unroll 1
    for (int h = 0; h < HH; h++) {
        __syncthreads();
        if (tid < 16)
            ((float4*)q_s)[tid] =
                ((const float4*)(q + (size_t)b * DD + h * DHEAD))[tid];
#pragma unroll
        for (int j = 0; j < 16; j++) {
            const int u = tid + j * 256;
            const int row = u >> 4, i4 = u & 15;
            float4 v = ((const float4*)Wk)[(size_t)(i0 + row) * 256 + h * 16 + i4];
            float* d = wk_s + row * 65 + i4 * 4;
            d[0] = v.x; d[1] = v.y; d[2] = v.z; d[3] = v.w;
        }
        __syncthreads();
        float s = 0.f;
        const float* wr = wk_s + tid * 65;
#pragma unroll 8
        for (int dd = 0; dd < 64; dd++) s += wr[dd] * q_s[dd];
        acc[h] = s * 0.125f;
    }
#pragma unroll
    for (int h = 0; h < HH; h++)
        wqt[((size_t)(b * HH + h)) * DD + i0 + tid] =
            __uint_as_float(f2tf32(acc[h]));
}

// ---------------------------------------------------------------------------
// sb[b][h] = (1/8) * bk[h,:].q^[b,h,:]
// ---------------------------------------------------------------------------
__global__ __launch_bounds__(512) void sb_kernel(
    const float* __restrict__ bk, const float* __restrict__ q,
    float* __restrict__ sb) {
    const int b = blockIdx.x;
    const int h = threadIdx.x >> 5;
    const int lane = threadIdx.x & 31;
    const int hd = h * DHEAD + lane * 2;
    float s = bk[hd] * q[b * DD + hd] + bk[hd + 1] * q[b * DD + hd + 1];
#pragma unroll
    for (int o = 16; o > 0; o >>= 1)
        s += __shfl_down_sync(0xFFFFFFFF, s, o);
    if (lane == 0) sb[b * HH + h] = s * 0.125f;
}

// ---------------------------------------------------------------------------
// scores via mma.sync tf32: per b, C[4096,16] = matrix[4096,1024] @ wq~T
// grid = (8 t-tiles of 512, 32 b), block = 256 (8 warps x 64-row m-tiles)
// On-the-fly tf32 rounding of matrix during staging; Kc=16.
// ---------------------------------------------------------------------------
#define SC_BS_FLOATS (16 * 1028)
#define SC_AS_FLOATS (512 * 20)
#define SC_SMEM ((SC_BS_FLOATS + SC_AS_FLOATS) * 4)   // 106752 B
__global__ __launch_bounds__(256, 1) void scores_mma_kernel(
    const float* __restrict__ matrix, const float* __restrict__ wqt,
    const float* __restrict__ sb, float* __restrict__ scores_out) {
    extern __shared__ float sm[];
    float* Bs = sm;                    // [16][1028]
    float* As = sm + SC_BS_FLOATS;     // [512][20]
    const int tid = threadIdx.x;
    const int wid = tid >> 5;
    const int lid = tid & 31;
    const int g = lid >> 2, tig = lid & 3;
    const int t0 = blockIdx.x * 512;
    const int b = blockIdx.y;
    const int wm = wid * 64;

    // Fill Bs (wq~ already tf32): cp.async, 16 units/thread
    {
        const uint32_t bsu = smem_u32(Bs);
#pragma unroll
        for (int j = 0; j < 16; j++) {
            const int u = tid + j * 256;
            const int h = u >> 8, c = u & 255;
            cp_async16(bsu + (uint32_t)(h * 1028 + c * 4) * 4,
                       wqt + ((size_t)(b * HH + h)) * DD + c * 4);
        }
        CP_COMMIT();
    }

    float acc[4][2][4];
#pragma unroll
    for (int i = 0; i < 4; i++)
#pragma unroll
        for (int j = 0; j < 2; j++)
#pragma unroll
            for (int q = 0; q < 4; q++) acc[i][j][q] = 0.f;

    const float4* mat4 = (const float4*)matrix;
    float4 pre[8];
    // load chunk 0
#pragma unroll
    for (int j = 0; j < 8; j++) {
        const int u = tid + j * 256;
        const int r = u >> 2, cu = u & 3;
        pre[j] = mat4[(size_t)(b * TT + t0 + r) * 256 + cu];
    }
    CP_WAIT0();
    __syncthreads();  // Bs ready

    for (int c = 0; c < 64; c++) {
        // store current chunk (rounded)
#pragma unroll
        for (int j = 0; j < 8; j++) {
            const int u = tid + j * 256;
            const int r = u >> 2, cu = u & 3;
            *(float4*)(As + r * 20 + cu * 4) = cvt4(pre[j]);
        }
        __syncthreads();
        // prefetch next chunk
        if (c < 63) {
#pragma unroll
            for (int j = 0; j < 8; j++) {
                const int u = tid + j * 256;
                const int r = u >> 2, cu = u & 3;
                pre[j] = mat4[(size_t)(b * TT + t0 + r) * 256 + (c + 1) * 4 + cu];
            }
        }
        // mma on current chunk
#pragma unroll
        for (int ks = 0; ks < 2; ks++) {
            const int kb = ks * 8;
            uint32_t af[4][4];
#pragma unroll
            for (int mf = 0; mf < 4; mf++) {
                const int rb = wm + mf * 16;
                af[mf][0] = __float_as_uint(As[(rb + g) * 20 + kb + tig]);
                af[mf][1] = __float_as_uint(As[(rb + g + 8) * 20 + kb + tig]);
                af[mf][2] = __float_as_uint(As[(rb + g) * 20 + kb + tig + 4]);
                af[mf][3] = __float_as_uint(As[(rb + g + 8) * 20 + kb + tig + 4]);
            }
            const int kg = c * 16 + kb;
#pragma unroll
            for (int nf = 0; nf < 2; nf++) {
                const int nb = nf * 8;
                const uint32_t b0 = __float_as_uint(Bs[(nb + g) * 1028 + kg + tig]);
                const uint32_t b1 = __float_as_uint(Bs[(nb + g) * 1028 + kg + tig + 4]);
#pragma unroll
                for (int mf = 0; mf < 4; mf++)
                    mma_tf32(acc[mf][nf], af[mf][0], af[mf][1], af[mf][2],
                             af[mf][3], b0, b1);
            }
        }
        __syncthreads();
    }

    // Epilogue
#pragma unroll
    for (int mf = 0; mf < 4; mf++) {
        const int t_lo = t0 + wm + mf * 16 + g;
#pragma unroll
        for (int nf = 0; nf < 2; nf++) {
            const int h0 = nf * 8 + 2 * tig;
            const float s0 = sb[b * HH + h0];
            const float s1 = sb[b * HH + h0 + 1];
            scores_out[((size_t)(b * HH + h0)) * TT + t_lo] = acc[mf][nf][0] + s0;
            scores_out[((size_t)(b * HH + h0 + 1)) * TT + t_lo] = acc[mf][nf][1] + s1;
            scores_out[((size_t)(b * HH + h0)) * TT + t_lo + 8] = acc[mf][nf][2] + s0;
            scores_out[((size_t)(b * HH + h0 + 1)) * TT + t_lo + 8] = acc[mf][nf][3] + s1;
        }
    }
}

// ---------------------------------------------------------------------------
// Masked softmax
// ---------------------------------------------------------------------------
__global__ __launch_bounds__(256) void softmax_kernel(
    const float* __restrict__ scores, const int* __restrict__ mask,
    float* __restrict__ attn_out) {
    const int h = blockIdx.x;
    const int b = blockIdx.y;
    const int tid = threadIdx.x;
    __shared__ float red[256];

    const int* mrow = mask + (size_t)b * TT;
    const size_t orow = ((size_t)(b * HH + h)) * TT;

    float sloc[16];
    float lmax = -3.0e38f;
#pragma unroll
    for (int it = 0; it < 16; it++) {
        const int t = tid + it * 256;
        const float s = scores[orow + t];
        const float ms = (mrow[t] > 0) ? s : -1e30f;
        sloc[it] = ms;
        lmax = fmaxf(lmax, ms);
    }
    red[tid] = lmax;
    __syncthreads();
    for (int st = 128; st > 0; st >>= 1) {
        if (tid < st) red[tid] = fmaxf(red[tid], red[tid + st]);
        __syncthreads();
    }
    const float mx = red[0];
    __syncthreads();

    float lsum = 0.f;
#pragma unroll
    for (int it = 0; it < 16; it++) {
        const float e = expf(sloc[it] - mx);
        sloc[it] = e;
        lsum += e;
    }
    red[tid] = lsum;
    __syncthreads();
    for (int st = 128; st > 0; st >>= 1) {
        if (tid < st) red[tid] += red[tid + st];
        __syncthreads();
    }
    const float inv = 1.0f / red[0];
#pragma unroll
    for (int it = 0; it < 16; it++)
        attn_out[orow + tid + it * 256] = sloc[it] * inv;
}

// ---------------------------------------------------------------------------
// r via mma.sync tf32: per b, r[16,1024] = attn[16,4096] @ matrix[4096,1024]
// grid = (8 n-tiles of 128, 32 b), block = 256; Kc=64, on-the-fly rounding.
// ---------------------------------------------------------------------------
__global__ __launch_bounds__(256) void rmix_kernel(
    const float* __restrict__ attn, const float* __restrict__ matrix,
    float* __restrict__ r) {
    __shared__ float Bs[64 * 136];   // matrix chunk [k][n], 34816 B
    __shared__ float As[16 * 68];    // attn chunk [h][k], 4352 B
    const int tid = threadIdx.x;
    const int wid = tid >> 5;
    const int lid = tid & 31;
    const int g = lid >> 2, tig = lid & 3;
    const int n0 = blockIdx.x * 128;
    const int b = blockIdx.y;
    const int wn = wid * 16;

    float acc[2][4];
#pragma unroll
    for (int j = 0; j < 2; j++)
#pragma unroll
        for (int q = 0; q < 4; q++) acc[j][q] = 0.f;

    const float4* mat4 = (const float4*)matrix;
    float4 preB[8];
    float4 preA;

    // load chunk 0
#pragma unroll
    for (int j = 0; j < 8; j++) {
        const int u = tid + j * 256;
        const int kr = u >> 5, cu = u & 31;
        preB[j] = mat4[(size_t)(b * TT + kr) * 256 + (n0 >> 2) + cu];
    }
    {
        const int h = tid >> 4, cu = tid & 15;
        preA = ((const float4*)attn)[((size_t)(b * HH + h)) * (TT / 4) + cu];
    }

    for (int c = 0; c < 64; c++) {
#pragma unroll
        for (int j = 0; j < 8; j++) {
            const int u = tid + j * 256;
            const int kr = u >> 5, cu = u & 31;
            *(float4*)(Bs + kr * 136 + cu * 4) = cvt4(preB[j]);
        }
        {
            const int h = tid >> 4, cu = tid & 15;
            *(float4*)(As + h * 68 + cu * 4) = cvt4(preA);
        }
        __syncthreads();
        if (c < 63) {
            const int k0n = (c + 1) * 64;
#pragma unroll
            for (int j = 0; j < 8; j++) {
                const int u = tid + j * 256;
                const int kr = u >> 5, cu = u & 31;
                preB[j] = mat4[(size_t)(b * TT + k0n + kr) * 256 + (n0 >> 2) + cu];
            }
            const int h = tid >> 4, cu = tid & 15;
            preA = ((const float4*)attn)[((size_t)(b * HH + h)) * (TT / 4) + (k0n >> 2) + cu];
        }
#pragma unroll
        for (int ks = 0; ks < 8; ks++) {
            const int kb = ks * 8;
            const uint32_t a0 = __float_as_uint(As[(g) * 68 + kb + tig]);
            const uint32_t a1 = __float_as_uint(As[(g + 8) * 68 + kb + tig]);
            const uint32_t a2 = __float_as_uint(As[(g) * 68 + kb + tig + 4]);
            const uint32_t a3 = __float_as_uint(As[(g + 8) * 68 + kb + tig + 4]);
#pragma unroll
            for (int nf = 0; nf < 2; nf++) {
                const int nc = wn + nf * 8 + g;
                const uint32_t b0 = __float_as_uint(Bs[(kb + tig) * 136 + nc]);
                const uint32_t b1 = __float_as_uint(Bs[(kb + tig + 4) * 136 + nc]);
                mma_tf32(acc[nf], a0, a1, a2, a3, b0, b1);
            }
        }
        __syncthreads();
    }

    // Epilogue: r[b][h][i]
#pragma unroll
    for (int nf = 0; nf < 2; nf++) {
        const int i = n0 + wn + nf * 8 + 2 * tig;
        float2 lo = {acc[nf][0], acc[nf][1]};
        float2 hi = {acc[nf][2], acc[nf][3]};
        *(float2*)(r + ((size_t)(b * HH + g)) * DD + i) = lo;
        *(float2*)(r + ((size_t)(b * HH + g + 8)) * DD + i) = hi;
    }
}

// ---------------------------------------------------------------------------
// ctx[b][hd] = sum_i r[b][hd>>6][i] * Wv[i][hd] + bv[hd]
// ---------------------------------------------------------------------------
__global__ __launch_bounds__(256) void ctx_kernel(
    const float* __restrict__ r, const float* __restrict__ Wv,
    const float* __restrict__ bv, float* __restrict__ ctx) {
    __shared__ float r_s[4 * DD];
    const int tid = threadIdx.x;
    const int hd = blockIdx.x * 256 + tid;
    const int b = blockIdx.y;
    const int h0 = (blockIdx.x * 256) >> 6;

    {
        const float4* src = (const float4*)(r + ((size_t)(b * HH + h0)) * DD);
        float4* dst = (float4*)r_s;
#pragma unroll
        for (int j = 0; j < 4; j++) dst[tid + j * 256] = src[tid + j * 256];
    }
    __syncthreads();

    const float* rr = r_s + ((hd >> 6) - h0) * DD;
    float acc = 0.f;
#pragma unroll 4
    for (int i = 0; i < DD; i++) acc += rr[i] * Wv[(size_t)i * DD + hd];
    ctx[(size_t)b * DD + hd] = acc + bv[hd];
}

// ---------------------------------------------------------------------------
// Launch
// ---------------------------------------------------------------------------
extern "C" void kernel_launch(void* const* d_in, const int* in_sizes, int n_in,
                              void* d_out, int out_size) {
    const float* vector = (const float*)d_in[0];
    const float* matrix = (const float*)d_in[1];
    const int*   mask   = (const int*)d_in[2];
    const float* Wq = (const float*)d_in[3];
    const float* bq = (const float*)d_in[4];
    const float* Wk = (const float*)d_in[5];
    const float* bk = (const float*)d_in[6];
    const float* Wv = (const float*)d_in[7];
    const float* bv = (const float*)d_in[8];
    const float* Wo = (const float*)d_in[9];
    const float* bo = (const float*)d_in[10];

    float* out = (float*)d_out;
    float* out_final  = out;
    float* attn_out   = out + (size_t)BB * DD;
    float* scores_out = attn_out + (size_t)BB * HH * TT;

    float *pq, *pwqt, *psb, *pr, *pctx, *ppp;
    cudaGetSymbolAddress((void**)&pq, g_q);
    cudaGetSymbolAddress((void**)&pwqt, g_wqt);
    cudaGetSymbolAddress((void**)&psb, g_sb);
    cudaGetSymbolAddress((void**)&pr, g_r);
    cudaGetSymbolAddress((void**)&pctx, g_ctx);
    cudaGetSymbolAddress((void**)&ppp, g_pp);

    cudaFuncSetAttribute(scores_mma_kernel,
                         cudaFuncAttributeMaxDynamicSharedMemorySize, SC_SMEM);
    cudaFuncSetAttribute(wqt_kernel,
                         cudaFuncAttributeMaxDynamicSharedMemorySize, WQT_SMEM);

    // q = vector @ Wq + bq (split-k)
    dim3 rpgrid(4, BB);
    rp_part_kernel<<<rpgrid, 256>>>(vector, Wq, ppp);
    rp_reduce_kernel<<<BB, 256>>>(ppp, bq, pq);

    // wq~ and sb
    dim3 wgrid(4, BB);
    wqt_kernel<<<wgrid, 256, WQT_SMEM>>>(Wk, pq, pwqt);
    sb_kernel<<<BB, 512>>>(bk, pq, psb);

    // scores = matrix @ wq~ + sb  (tf32 mma)
    dim3 sgrid(8, BB);
    scores_mma_kernel<<<sgrid, 256, SC_SMEM>>>(matrix, pwqt, psb, scores_out);

    // attn = masked softmax(scores)
    dim3 smgrid(HH, BB);
    softmax_kernel<<<smgrid, 256>>>(scores_out, mask, attn_out);

    // r = attn @ matrix (tf32 mma)
    dim3 rgrid(8, BB);
    rmix_kernel<<<rgrid, 256>>>(attn_out, matrix, pr);

    // ctx = r @ Wv + bv
    dim3 cgrid(4, BB);
    ctx_kernel<<<cgrid, 256>>>(pr, Wv, bv, pctx);

    // out = ctx @ Wo + bo (split-k)
    rp_part_kernel<<<rpgrid, 256>>>(pctx, Wo, ppp);
    rp_reduce_kernel<<<BB, 256>>>(ppp, bo, out_final);
}

// round 8
// speedup vs baseline: 22.5484x; 1.1161x over previous
#include <cuda_runtime.h>
#include <math.h>
#include <stdint.h>

#define BB 32
#define TT 4096
#define DD 1024
#define HH 16
#define DHEAD 64

// Scratch (device globals; no allocations)
__device__ float g_q[BB * DD];
__device__ float g_wqt[BB * HH * DD];   // wq~[b][h][i], tf32-rounded, incl /8
__device__ float g_sb[BB * HH];
__device__ float g_r[BB * HH * DD];     // r[b][h][i]
__device__ float g_ctx[BB * DD];
__device__ float g_pp[BB * 4 * DD];     // rowproj partials

// ---------------------------------------------------------------------------
__device__ __forceinline__ uint32_t f2tf32(float x) {
    uint32_t u;
    asm("cvt.rna.tf32.f32 %0, %1;" : "=r"(u) : "f"(x));
    return u;
}
__device__ __forceinline__ void cp_async16(uint32_t sdst, const void* gsrc) {
    asm volatile("cp.async.cg.shared.global [%0], [%1], 16;" :: "r"(sdst), "l"(gsrc));
}
#define CP_COMMIT() asm volatile("cp.async.commit_group;" ::: "memory")
#define CP_WAIT0()  asm volatile("cp.async.wait_group 0;" ::: "memory")
__device__ __forceinline__ uint32_t smem_u32(const void* p) {
    uint32_t a;
    asm("{ .reg .u64 t; cvta.to.shared.u64 t, %1; cvt.u32.u64 %0, t; }"
        : "=r"(a) : "l"(p));
    return a;
}
__device__ __forceinline__ void mma_tf32(
    float* c, uint32_t a0, uint32_t a1, uint32_t a2, uint32_t a3,
    uint32_t b0, uint32_t b1) {
    asm volatile(
        "mma.sync.aligned.m16n8k8.row.col.f32.tf32.tf32.f32 "
        "{%0,%1,%2,%3}, {%4,%5,%6,%7}, {%8,%9}, {%0,%1,%2,%3};"
        : "+f"(c[0]), "+f"(c[1]), "+f"(c[2]), "+f"(c[3])
        : "r"(a0), "r"(a1), "r"(a2), "r"(a3), "r"(b0), "r"(b1));
}
__device__ __forceinline__ float4 cvt4(float4 v) {
    float4 o;
    o.x = __uint_as_float(f2tf32(v.x));
    o.y = __uint_as_float(f2tf32(v.y));
    o.z = __uint_as_float(f2tf32(v.z));
    o.w = __uint_as_float(f2tf32(v.w));
    return o;
}

// ---------------------------------------------------------------------------
// Split row projection: partials over k-slices of 256, then reduce.
// ---------------------------------------------------------------------------
__global__ __launch_bounds__(256) void rp_part_kernel(
    const float* __restrict__ X, const float* __restrict__ W,
    float* __restrict__ pp) {
    __shared__ float xs[256];
    const int s = blockIdx.x;
    const int b = blockIdx.y;
    const int tid = threadIdx.x;
    xs[tid] = X[(size_t)b * DD + s * 256 + tid];
    __syncthreads();
    float a0 = 0.f, a1 = 0.f, a2 = 0.f, a3 = 0.f;
#pragma unroll 8
    for (int k = 0; k < 256; k++) {
        const float xv = xs[k];
        const float* wr = W + (size_t)(s * 256 + k) * DD;
        a0 += xv * wr[tid];
        a1 += xv * wr[tid + 256];
        a2 += xv * wr[tid + 512];
        a3 += xv * wr[tid + 768];
    }
    float* o = pp + (size_t)(b * 4 + s) * DD;
    o[tid] = a0; o[tid + 256] = a1; o[tid + 512] = a2; o[tid + 768] = a3;
}

__global__ __launch_bounds__(256) void rp_reduce_kernel(
    const float* __restrict__ pp, const float* __restrict__ bias,
    float* __restrict__ Y) {
    const int b = blockIdx.x;
    const int tid = threadIdx.x;
#pragma unroll
    for (int j = 0; j < 4; j++) {
        const int c = tid + j * 256;
        float s = bias[c];
#pragma unroll
        for (int sl = 0; sl < 4; sl++) s += pp[(size_t)(b * 4 + sl) * DD + c];
        Y[(size_t)b * DD + c] = s;
    }
}

// ---------------------------------------------------------------------------
// wq~[b][h][i] = tf32( (1/8) * sum_d Wk[i][h*64+d] * q[b][h*64+d] )
// ---------------------------------------------------------------------------
#define WQT_SMEM ((256 * 65 + 64) * 4)
__global__ __launch_bounds__(256) void wqt_kernel(
    const float* __restrict__ Wk, const float* __restrict__ q,
    float* __restrict__ wqt) {
    extern __shared__ float sm[];
    float* wk_s = sm;
    float* q_s  = sm + 256 * 65;
    const int tid = threadIdx.x;
    const int i0 = blockIdx.x * 256;
    const int b = blockIdx.y;

    float acc[HH];
#pragma unroll 1
    for (int h = 0; h < HH; h++) {
        __syncthreads();
        if (tid < 16)
            ((float4*)q_s)[tid] =
                ((const float4*)(q + (size_t)b * DD + h * DHEAD))[tid];
#pragma unroll
        for (int j = 0; j < 16; j++) {
            const int u = tid + j * 256;
            const int row = u >> 4, i4 = u & 15;
            float4 v = ((const float4*)Wk)[(size_t)(i0 + row) * 256 + h * 16 + i4];
            float* d = wk_s + row * 65 + i4 * 4;
            d[0] = v.x; d[1] = v.y; d[2] = v.z; d[3] = v.w;
        }
        __syncthreads();
        float s = 0.f;
        const float* wr = wk_s + tid * 65;
#pragma unroll 8
        for (int dd = 0; dd < 64; dd++) s += wr[dd] * q_s[dd];
        acc[h] = s * 0.125f;
    }
#pragma unroll
    for (int h = 0; h < HH; h++)
        wqt[((size_t)(b * HH + h)) * DD + i0 + tid] =
            __uint_as_float(f2tf32(acc[h]));
}

// ---------------------------------------------------------------------------
// sb[b][h] = (1/8) * bk[h,:].q^[b,h,:]
// ---------------------------------------------------------------------------
__global__ __launch_bounds__(512) void sb_kernel(
    const float* __restrict__ bk, const float* __restrict__ q,
    float* __restrict__ sb) {
    const int b = blockIdx.x;
    const int h = threadIdx.x >> 5;
    const int lane = threadIdx.x & 31;
    const int hd = h * DHEAD + lane * 2;
    float s = bk[hd] * q[b * DD + hd] + bk[hd + 1] * q[b * DD + hd + 1];
#pragma unroll
    for (int o = 16; o > 0; o >>= 1)
        s += __shfl_down_sync(0xFFFFFFFF, s, o);
    if (lane == 0) sb[b * HH + h] = s * 0.125f;
}

// ---------------------------------------------------------------------------
// scores via mma.sync tf32: per b, C[4096,16] = matrix[4096,1024] @ wq~T
// grid = (8 t-tiles of 512, 32 b), block = 256 (8 warps x 64-row m-tiles)
// 2-stage pipeline, 1 barrier/chunk. A: on-the-fly tf32 rounding (LDG->STS).
// B (wq~, already tf32): per-chunk cp.async double buffer. Kc=16.
// ---------------------------------------------------------------------------
#define SC_AS_STRIDE 20
#define SC_AS_FLOATS (512 * SC_AS_STRIDE)         // per stage
#define SC_BS_FLOATS (16 * SC_AS_STRIDE)          // per stage
#define SC_SMEM ((2 * SC_AS_FLOATS + 2 * SC_BS_FLOATS) * 4)   // 84480 B
__global__ __launch_bounds__(256, 1) void scores_mma_kernel(
    const float* __restrict__ matrix, const float* __restrict__ wqt,
    const float* __restrict__ sb, float* __restrict__ scores_out) {
    extern __shared__ float sm[];
    float* As[2] = {sm, sm + SC_AS_FLOATS};
    float* Bs[2] = {sm + 2 * SC_AS_FLOATS, sm + 2 * SC_AS_FLOATS + SC_BS_FLOATS};
    const uint32_t bsu[2] = {smem_u32(Bs[0]), smem_u32(Bs[1])};
    const int tid = threadIdx.x;
    const int wid = tid >> 5;
    const int lid = tid & 31;
    const int g = lid >> 2, tig = lid & 3;
    const int t0 = blockIdx.x * 512;
    const int b = blockIdx.y;
    const int wm = wid * 64;

    const float4* mat4 = (const float4*)matrix;
    const float* wqb = wqt + (size_t)b * HH * DD;

    // B chunk loader: 16h x 16k floats = 64x16B, threads 0..63
    auto loadB = [&](int c, int s) {
        if (tid < 64) {
            const int h = tid >> 2, k4 = tid & 3;
            cp_async16(bsu[s] + (uint32_t)(h * SC_AS_STRIDE + k4 * 4) * 4,
                       wqb + (size_t)h * DD + c * 16 + k4 * 4);
        }
        CP_COMMIT();
    };

    float acc[4][2][4];
#pragma unroll
    for (int i = 0; i < 4; i++)
#pragma unroll
        for (int j = 0; j < 2; j++)
#pragma unroll
            for (int q = 0; q < 4; q++) acc[i][j][q] = 0.f;

    float4 pre[8];
    // Prologue: chunk0 into stage 0, chunk1 into regs
    loadB(0, 0);
#pragma unroll
    for (int j = 0; j < 8; j++) {
        const int u = tid + j * 256;
        const int r = u >> 2, cu = u & 3;
        pre[j] = mat4[(size_t)(b * TT + t0 + r) * 256 + cu];
    }
#pragma unroll
    for (int j = 0; j < 8; j++) {
        const int u = tid + j * 256;
        const int r = u >> 2, cu = u & 3;
        *(float4*)(As[0] + r * SC_AS_STRIDE + cu * 4) = cvt4(pre[j]);
    }
#pragma unroll
    for (int j = 0; j < 8; j++) {
        const int u = tid + j * 256;
        const int r = u >> 2, cu = u & 3;
        pre[j] = mat4[(size_t)(b * TT + t0 + r) * 256 + 4 + cu];
    }
    CP_WAIT0();
    __syncthreads();

    for (int c = 0; c < 64; c++) {
        const int s = c & 1;
        if (c < 63) {
            loadB(c + 1, s ^ 1);
#pragma unroll
            for (int j = 0; j < 8; j++) {
                const int u = tid + j * 256;
                const int r = u >> 2, cu = u & 3;
                *(float4*)(As[s ^ 1] + r * SC_AS_STRIDE + cu * 4) = cvt4(pre[j]);
            }
        }
        if (c < 62) {
#pragma unroll
            for (int j = 0; j < 8; j++) {
                const int u = tid + j * 256;
                const int r = u >> 2, cu = u & 3;
                pre[j] = mat4[(size_t)(b * TT + t0 + r) * 256 + (c + 2) * 4 + cu];
            }
        }
        const float* As_s = As[s];
        const float* Bs_s = Bs[s];
#pragma unroll
        for (int ks = 0; ks < 2; ks++) {
            const int kb = ks * 8;
            uint32_t af[4][4];
#pragma unroll
            for (int mf = 0; mf < 4; mf++) {
                const int rb = wm + mf * 16;
                af[mf][0] = __float_as_uint(As_s[(rb + g) * SC_AS_STRIDE + kb + tig]);
                af[mf][1] = __float_as_uint(As_s[(rb + g + 8) * SC_AS_STRIDE + kb + tig]);
                af[mf][2] = __float_as_uint(As_s[(rb + g) * SC_AS_STRIDE + kb + tig + 4]);
                af[mf][3] = __float_as_uint(As_s[(rb + g + 8) * SC_AS_STRIDE + kb + tig + 4]);
            }
#pragma unroll
            for (int nf = 0; nf < 2; nf++) {
                const int nb = nf * 8;
                const uint32_t b0 = __float_as_uint(Bs_s[(nb + g) * SC_AS_STRIDE + kb + tig]);
                const uint32_t b1 = __float_as_uint(Bs_s[(nb + g) * SC_AS_STRIDE + kb + tig + 4]);
#pragma unroll
                for (int mf = 0; mf < 4; mf++)
                    mma_tf32(acc[mf][nf], af[mf][0], af[mf][1], af[mf][2],
                             af[mf][3], b0, b1);
            }
        }
        CP_WAIT0();
        __syncthreads();
    }

    // Epilogue
#pragma unroll
    for (int mf = 0; mf < 4; mf++) {
        const int t_lo = t0 + wm + mf * 16 + g;
#pragma unroll
        for (int nf = 0; nf < 2; nf++) {
            const int h0 = nf * 8 + 2 * tig;
            const float s0 = sb[b * HH + h0];
            const float s1 = sb[b * HH + h0 + 1];
            scores_out[((size_t)(b * HH + h0)) * TT + t_lo] = acc[mf][nf][0] + s0;
            scores_out[((size_t)(b * HH + h0 + 1)) * TT + t_lo] = acc[mf][nf][1] + s1;
            scores_out[((size_t)(b * HH + h0)) * TT + t_lo + 8] = acc[mf][nf][2] + s0;
            scores_out[((size_t)(b * HH + h0 + 1)) * TT + t_lo + 8] = acc[mf][nf][3] + s1;
        }
    }
}

// ---------------------------------------------------------------------------
// Masked softmax
// ---------------------------------------------------------------------------
__global__ __launch_bounds__(256) void softmax_kernel(
    const float* __restrict__ scores, const int* __restrict__ mask,
    float* __restrict__ attn_out) {
    const int h = blockIdx.x;
    const int b = blockIdx.y;
    const int tid = threadIdx.x;
    __shared__ float red[256];

    const int* mrow = mask + (size_t)b * TT;
    const size_t orow = ((size_t)(b * HH + h)) * TT;

    float sloc[16];
    float lmax = -3.0e38f;
#pragma unroll
    for (int it = 0; it < 16; it++) {
        const int t = tid + it * 256;
        const float s = scores[orow + t];
        const float ms = (mrow[t] > 0) ? s : -1e30f;
        sloc[it] = ms;
        lmax = fmaxf(lmax, ms);
    }
    red[tid] = lmax;
    __syncthreads();
    for (int st = 128; st > 0; st >>= 1) {
        if (tid < st) red[tid] = fmaxf(red[tid], red[tid + st]);
        __syncthreads();
    }
    const float mx = red[0];
    __syncthreads();

    float lsum = 0.f;
#pragma unroll
    for (int it = 0; it < 16; it++) {
        const float e = __expf(sloc[it] - mx);
        sloc[it] = e;
        lsum += e;
    }
    red[tid] = lsum;
    __syncthreads();
    for (int st = 128; st > 0; st >>= 1) {
        if (tid < st) red[tid] += red[tid + st];
        __syncthreads();
    }
    const float inv = 1.0f / red[0];
#pragma unroll
    for (int it = 0; it < 16; it++)
        attn_out[orow + tid + it * 256] = sloc[it] * inv;
}

// ---------------------------------------------------------------------------
// r via mma.sync tf32: per b, r[16,1024] = attn[16,4096] @ matrix[4096,1024]
// grid = (8 n-tiles of 128, 32 b), block = 256; Kc=64.
// 2-stage pipeline, 1 barrier/chunk, on-the-fly tf32 rounding.
// ---------------------------------------------------------------------------
#define RM_BS_FLOATS (64 * 136)
#define RM_AS_FLOATS (16 * 68)
__global__ __launch_bounds__(256) void rmix_kernel(
    const float* __restrict__ attn, const float* __restrict__ matrix,
    float* __restrict__ r) {
    __shared__ float Bst[2][RM_BS_FLOATS];
    __shared__ float Ast[2][RM_AS_FLOATS];
    const int tid = threadIdx.x;
    const int wid = tid >> 5;
    const int lid = tid & 31;
    const int g = lid >> 2, tig = lid & 3;
    const int n0 = blockIdx.x * 128;
    const int b = blockIdx.y;
    const int wn = wid * 16;

    float acc[2][4];
#pragma unroll
    for (int j = 0; j < 2; j++)
#pragma unroll
        for (int q = 0; q < 4; q++) acc[j][q] = 0.f;

    const float4* mat4 = (const float4*)matrix;
    const float4* attn4 = (const float4*)(attn + ((size_t)b * HH) * TT);
    float4 preB[8];
    float4 preA;
    const int ha = tid >> 4, cua = tid & 15;

    auto ldgChunk = [&](int c) {
        const int k0 = c * 64;
#pragma unroll
        for (int j = 0; j < 8; j++) {
            const int u = tid + j * 256;
            const int kr = u >> 5, cu = u & 31;
            preB[j] = mat4[(size_t)(b * TT + k0 + kr) * 256 + (n0 >> 2) + cu];
        }
        preA = attn4[(size_t)ha * (TT / 4) + (k0 >> 2) + cua];
    };
    auto stsChunk = [&](int s) {
#pragma unroll
        for (int j = 0; j < 8; j++) {
            const int u = tid + j * 256;
            const int kr = u >> 5, cu = u & 31;
            *(float4*)(&Bst[s][kr * 136 + cu * 4]) = cvt4(preB[j]);
        }
        *(float4*)(&Ast[s][ha * 68 + cua * 4]) = cvt4(preA);
    };

    // Prologue
    ldgChunk(0);
    stsChunk(0);
    ldgChunk(1);
    __syncthreads();

    for (int c = 0; c < 64; c++) {
        const int s = c & 1;
        if (c < 63) stsChunk(s ^ 1);
        if (c < 62) ldgChunk(c + 2);
        const float* As_s = Ast[s];
        const float* Bs_s = Bst[s];
#pragma unroll
        for (int ks = 0; ks < 8; ks++) {
            const int kb = ks * 8;
            const uint32_t a0 = __float_as_uint(As_s[(g) * 68 + kb + tig]);
            const uint32_t a1 = __float_as_uint(As_s[(g + 8) * 68 + kb + tig]);
            const uint32_t a2 = __float_as_uint(As_s[(g) * 68 + kb + tig + 4]);
            const uint32_t a3 = __float_as_uint(As_s[(g + 8) * 68 + kb + tig + 4]);
#pragma unroll
            for (int nf = 0; nf < 2; nf++) {
                const int nc = wn + nf * 8 + g;
                const uint32_t b0 = __float_as_uint(Bs_s[(kb + tig) * 136 + nc]);
                const uint32_t b1 = __float_as_uint(Bs_s[(kb + tig + 4) * 136 + nc]);
                mma_tf32(acc[nf], a0, a1, a2, a3, b0, b1);
            }
        }
        __syncthreads();
    }

    // Epilogue: r[b][h][i]
#pragma unroll
    for (int nf = 0; nf < 2; nf++) {
        const int i = n0 + wn + nf * 8 + 2 * tig;
        float2 lo = {acc[nf][0], acc[nf][1]};
        float2 hi = {acc[nf][2], acc[nf][3]};
        *(float2*)(r + ((size_t)(b * HH + g)) * DD + i) = lo;
        *(float2*)(r + ((size_t)(b * HH + g + 8)) * DD + i) = hi;
    }
}

// ---------------------------------------------------------------------------
// ctx[b][hd] = sum_i r[b][hd>>6][i] * Wv[i][hd] + bv[hd]
// ---------------------------------------------------------------------------
__global__ __launch_bounds__(256) void ctx_kernel(
    const float* __restrict__ r, const float* __restrict__ Wv,
    const float* __restrict__ bv, float* __restrict__ ctx) {
    __shared__ float r_s[4 * DD];
    const int tid = threadIdx.x;
    const int hd = blockIdx.x * 256 + tid;
    const int b = blockIdx.y;
    const int h0 = (blockIdx.x * 256) >> 6;

    {
        const float4* src = (const float4*)(r + ((size_t)(b * HH + h0)) * DD);
        float4* dst = (float4*)r_s;
#pragma unroll
        for (int j = 0; j < 4; j++) dst[tid + j * 256] = src[tid + j * 256];
    }
    __syncthreads();

    const float* rr = r_s + ((hd >> 6) - h0) * DD;
    float acc = 0.f;
#pragma unroll 8
    for (int i = 0; i < DD; i++) acc += rr[i] * Wv[(size_t)i * DD + hd];
    ctx[(size_t)b * DD + hd] = acc + bv[hd];
}

// ---------------------------------------------------------------------------
// Launch
// ---------------------------------------------------------------------------
extern "C" void kernel_launch(void* const* d_in, const int* in_sizes, int n_in,
                              void* d_out, int out_size) {
    const float* vector = (const float*)d_in[0];
    const float* matrix = (const float*)d_in[1];
    const int*   mask   = (const int*)d_in[2];
    const float* Wq = (const float*)d_in[3];
    const float* bq = (const float*)d_in[4];
    const float* Wk = (const float*)d_in[5];
    const float* bk = (const float*)d_in[6];
    const float* Wv = (const float*)d_in[7];
    const float* bv = (const float*)d_in[8];
    const float* Wo = (const float*)d_in[9];
    const float* bo = (const float*)d_in[10];

    float* out = (float*)d_out;
    float* out_final  = out;
    float* attn_out   = out + (size_t)BB * DD;
    float* scores_out = attn_out + (size_t)BB * HH * TT;

    float *pq, *pwqt, *psb, *pr, *pctx, *ppp;
    cudaGetSymbolAddress((void**)&pq, g_q);
    cudaGetSymbolAddress((void**)&pwqt, g_wqt);
    cudaGetSymbolAddress((void**)&psb, g_sb);
    cudaGetSymbolAddress((void**)&pr, g_r);
    cudaGetSymbolAddress((void**)&pctx, g_ctx);
    cudaGetSymbolAddress((void**)&ppp, g_pp);

    cudaFuncSetAttribute(scores_mma_kernel,
                         cudaFuncAttributeMaxDynamicSharedMemorySize, SC_SMEM);
    cudaFuncSetAttribute(wqt_kernel,
                         cudaFuncAttributeMaxDynamicSharedMemorySize, WQT_SMEM);

    // q = vector @ Wq + bq (split-k)
    dim3 rpgrid(4, BB);
    rp_part_kernel<<<rpgrid, 256>>>(vector, Wq, ppp);
    rp_reduce_kernel<<<BB, 256>>>(ppp, bq, pq);

    // wq~ and sb
    dim3 wgrid(4, BB);
    wqt_kernel<<<wgrid, 256, WQT_SMEM>>>(Wk, pq, pwqt);
    sb_kernel<<<BB, 512>>>(bk, pq, psb);

    // scores = matrix @ wq~ + sb  (tf32 mma, pipelined)
    dim3 sgrid(8, BB);
    scores_mma_kernel<<<sgrid, 256, SC_SMEM>>>(matrix, pwqt, psb, scores_out);

    // attn = masked softmax(scores)
    dim3 smgrid(HH, BB);
    softmax_kernel<<<smgrid, 256>>>(scores_out, mask, attn_out);

    // r = attn @ matrix (tf32 mma, pipelined)
    dim3 rgrid(8, BB);
    rmix_kernel<<<rgrid, 256>>>(attn_out, matrix, pr);

    // ctx = r @ Wv + bv
    dim3 cgrid(4, BB);
    ctx_kernel<<<cgrid, 256>>>(pr, Wv, bv, pctx);

    // out = ctx @ Wo + bo (split-k)
    rp_part_kernel<<<rpgrid, 256>>>(pctx, Wo, ppp);
    rp_reduce_kernel<<<BB, 256>>>(ppp, bo, out_final);
}

// round 10
// speedup vs baseline: 23.1040x; 1.0246x over previous
#include <cuda_runtime.h>
#include <math.h>
#include <stdint.h>

#define BB 32
#define TT 4096
#define DD 1024
#define HH 16
#define DHEAD 64

// Scratch (device globals; no allocations)
__device__ float g_q[BB * DD];
__device__ float g_wqt[BB * HH * DD];   // wq~[b][h][i], tf32-rounded, incl /8
__device__ float g_sb[BB * HH];
__device__ float g_r[BB * HH * DD];     // r[b][h][i]
__device__ float g_ctx[BB * DD];
__device__ float g_pp[BB * 4 * DD];     // rowproj partials

// ---------------------------------------------------------------------------
__device__ __forceinline__ uint32_t f2tf32(float x) {
    uint32_t u;
    asm("cvt.rna.tf32.f32 %0, %1;" : "=r"(u) : "f"(x));
    return u;
}
__device__ __forceinline__ void mma_tf32(
    float* c, uint32_t a0, uint32_t a1, uint32_t a2, uint32_t a3,
    uint32_t b0, uint32_t b1) {
    asm volatile(
        "mma.sync.aligned.m16n8k8.row.col.f32.tf32.tf32.f32 "
        "{%0,%1,%2,%3}, {%4,%5,%6,%7}, {%8,%9}, {%0,%1,%2,%3};"
        : "+f"(c[0]), "+f"(c[1]), "+f"(c[2]), "+f"(c[3])
        : "r"(a0), "r"(a1), "r"(a2), "r"(a3), "r"(b0), "r"(b1));
}
__device__ __forceinline__ float4 cvt4(float4 v) {
    float4 o;
    o.x = __uint_as_float(f2tf32(v.x));
    o.y = __uint_as_float(f2tf32(v.y));
    o.z = __uint_as_float(f2tf32(v.z));
    o.w = __uint_as_float(f2tf32(v.w));
    return o;
}

// ---------------------------------------------------------------------------
// Split row projection: partials over k-slices of 256, then reduce.
// ---------------------------------------------------------------------------
__global__ __launch_bounds__(256) void rp_part_kernel(
    const float* __restrict__ X, const float* __restrict__ W,
    float* __restrict__ pp) {
    __shared__ float xs[256];
    const int s = blockIdx.x;
    const int b = blockIdx.y;
    const int tid = threadIdx.x;
    xs[tid] = X[(size_t)b * DD + s * 256 + tid];
    __syncthreads();
    float a0 = 0.f, a1 = 0.f, a2 = 0.f, a3 = 0.f;
#pragma unroll 8
    for (int k = 0; k < 256; k++) {
        const float xv = xs[k];
        const float* wr = W + (size_t)(s * 256 + k) * DD;
        a0 += xv * wr[tid];
        a1 += xv * wr[tid + 256];
        a2 += xv * wr[tid + 512];
        a3 += xv * wr[tid + 768];
    }
    float* o = pp + (size_t)(b * 4 + s) * DD;
    o[tid] = a0; o[tid + 256] = a1; o[tid + 512] = a2; o[tid + 768] = a3;
}

__global__ __launch_bounds__(256) void rp_reduce_kernel(
    const float* __restrict__ pp, const float* __restrict__ bias,
    float* __restrict__ Y) {
    const int b = blockIdx.x;
    const int tid = threadIdx.x;
#pragma unroll
    for (int j = 0; j < 4; j++) {
        const int c = tid + j * 256;
        float s = bias[c];
#pragma unroll
        for (int sl = 0; sl < 4; sl++) s += pp[(size_t)(b * 4 + sl) * DD + c];
        Y[(size_t)b * DD + c] = s;
    }
}

// ---------------------------------------------------------------------------
// wq~[b][h][i] = tf32( (1/8) * sum_d Wk[i][h*64+d] * q[b][h*64+d] )
// ---------------------------------------------------------------------------
#define WQT_SMEM ((256 * 65 + 64) * 4)
__global__ __launch_bounds__(256) void wqt_kernel(
    const float* __restrict__ Wk, const float* __restrict__ q,
    float* __restrict__ wqt) {
    extern __shared__ float sm[];
    float* wk_s = sm;
    float* q_s  = sm + 256 * 65;
    const int tid = threadIdx.x;
    const int i0 = blockIdx.x * 256;
    const int b = blockIdx.y;

    float acc[HH];
#pragma unroll 1
    for (int h = 0; h < HH; h++) {
        __syncthreads();
        if (tid < 16)
            ((float4*)q_s)[tid] =
                ((const float4*)(q + (size_t)b * DD + h * DHEAD))[tid];
#pragma unroll
        for (int j = 0; j < 16; j++) {
            const int u = tid + j * 256;
            const int row = u >> 4, i4 = u & 15;
            float4 v = ((const float4*)Wk)[(size_t)(i0 + row) * 256 + h * 16 + i4];
            float* d = wk_s + row * 65 + i4 * 4;
            d[0] = v.x; d[1] = v.y; d[2] = v.z; d[3] = v.w;
        }
        __syncthreads();
        float s = 0.f;
        const float* wr = wk_s + tid * 65;
#pragma unroll 8
        for (int dd = 0; dd < 64; dd++) s += wr[dd] * q_s[dd];
        acc[h] = s * 0.125f;
    }
#pragma unroll
    for (int h = 0; h < HH; h++)
        wqt[((size_t)(b * HH + h)) * DD + i0 + tid] =
            __uint_as_float(f2tf32(acc[h]));
}

// ---------------------------------------------------------------------------
// sb[b][h] = (1/8) * bk[h,:].q^[b,h,:]
// ---------------------------------------------------------------------------
__global__ __launch_bounds__(512) void sb_kernel(
    const float* __restrict__ bk, const float* __restrict__ q,
    float* __restrict__ sb) {
    const int b = blockIdx.x;
    const int h = threadIdx.x >> 5;
    const int lane = threadIdx.x & 31;
    const int hd = h * DHEAD + lane * 2;
    float s = bk[hd] * q[b * DD + hd] + bk[hd + 1] * q[b * DD + hd + 1];
#pragma unroll
    for (int o = 16; o > 0; o >>= 1)
        s += __shfl_down_sync(0xFFFFFFFF, s, o);
    if (lane == 0) sb[b * HH + h] = s * 0.125f;
}

// ---------------------------------------------------------------------------
// scores via mma.sync tf32: per b, C[4096,16] = matrix[4096,1024] @ wq~T
// grid = (16 t-tiles of 256, 32 b), block = 256 (8 warps x 32-row m-tiles)
// 2-stage, 1 barrier/chunk; A AND B both register-prefetched (no cp.async).
// Kc=16. B chunk = 256 floats = 1 float/thread.
// ---------------------------------------------------------------------------
#define SC_STRIDE 20
__global__ __launch_bounds__(256) void scores_mma_kernel(
    const float* __restrict__ matrix, const float* __restrict__ wqt,
    const float* __restrict__ sb, float* __restrict__ scores_out) {
    __shared__ float As[2][256 * SC_STRIDE];
    __shared__ float Bs[2][16 * SC_STRIDE];
    const int tid = threadIdx.x;
    const int wid = tid >> 5;
    const int lid = tid & 31;
    const int g = lid >> 2, tig = lid & 3;
    const int t0 = blockIdx.x * 256;
    const int b = blockIdx.y;
    const int wm = wid * 32;
    const int hb = tid >> 4, kb4 = tid & 15;   // B-load coords

    const float4* mat4 = (const float4*)matrix;
    const float* wqb = wqt + (size_t)b * HH * DD;

    float4 pre[4];
    float bpre;

    auto ldgChunk = [&](int c) {
#pragma unroll
        for (int j = 0; j < 4; j++) {
            const int u = tid + j * 256;
            const int r = u >> 2, cu = u & 3;
            pre[j] = mat4[(size_t)(b * TT + t0 + r) * 256 + c * 4 + cu];
        }
        bpre = wqb[(size_t)hb * DD + c * 16 + kb4];
    };
    auto stsChunk = [&](int s) {
#pragma unroll
        for (int j = 0; j < 4; j++) {
            const int u = tid + j * 256;
            const int r = u >> 2, cu = u & 3;
            *(float4*)(&As[s][r * SC_STRIDE + cu * 4]) = cvt4(pre[j]);
        }
        Bs[s][hb * SC_STRIDE + kb4] = bpre;  // already tf32
    };

    float acc[2][2][4];
#pragma unroll
    for (int i = 0; i < 2; i++)
#pragma unroll
        for (int j = 0; j < 2; j++)
#pragma unroll
            for (int q = 0; q < 4; q++) acc[i][j][q] = 0.f;

    // Prologue
    ldgChunk(0);
    stsChunk(0);
    ldgChunk(1);
    __syncthreads();

    for (int c = 0; c < 64; c++) {
        const int s = c & 1;
        if (c < 63) stsChunk(s ^ 1);
        if (c < 62) ldgChunk(c + 2);
        const float* As_s = As[s];
        const float* Bs_s = Bs[s];
#pragma unroll
        for (int ks = 0; ks < 2; ks++) {
            const int kb = ks * 8;
            uint32_t af[2][4];
#pragma unroll
            for (int mf = 0; mf < 2; mf++) {
                const int rb = wm + mf * 16;
                af[mf][0] = __float_as_uint(As_s[(rb + g) * SC_STRIDE + kb + tig]);
                af[mf][1] = __float_as_uint(As_s[(rb + g + 8) * SC_STRIDE + kb + tig]);
                af[mf][2] = __float_as_uint(As_s[(rb + g) * SC_STRIDE + kb + tig + 4]);
                af[mf][3] = __float_as_uint(As_s[(rb + g + 8) * SC_STRIDE + kb + tig + 4]);
            }
#pragma unroll
            for (int nf = 0; nf < 2; nf++) {
                const int nb = nf * 8;
                const uint32_t b0 = __float_as_uint(Bs_s[(nb + g) * SC_STRIDE + kb + tig]);
                const uint32_t b1 = __float_as_uint(Bs_s[(nb + g) * SC_STRIDE + kb + tig + 4]);
#pragma unroll
                for (int mf = 0; mf < 2; mf++)
                    mma_tf32(acc[mf][nf], af[mf][0], af[mf][1], af[mf][2],
                             af[mf][3], b0, b1);
            }
        }
        __syncthreads();
    }

    // Epilogue
#pragma unroll
    for (int mf = 0; mf < 2; mf++) {
        const int t_lo = t0 + wm + mf * 16 + g;
#pragma unroll
        for (int nf = 0; nf < 2; nf++) {
            const int h0 = nf * 8 + 2 * tig;
            const float s0 = sb[b * HH + h0];
            const float s1 = sb[b * HH + h0 + 1];
            scores_out[((size_t)(b * HH + h0)) * TT + t_lo] = acc[mf][nf][0] + s0;
            scores_out[((size_t)(b * HH + h0 + 1)) * TT + t_lo] = acc[mf][nf][1] + s1;
            scores_out[((size_t)(b * HH + h0)) * TT + t_lo + 8] = acc[mf][nf][2] + s0;
            scores_out[((size_t)(b * HH + h0 + 1)) * TT + t_lo + 8] = acc[mf][nf][3] + s1;
        }
    }
}

// ---------------------------------------------------------------------------
// Masked softmax
// ---------------------------------------------------------------------------
__global__ __launch_bounds__(256) void softmax_kernel(
    const float* __restrict__ scores, const int* __restrict__ mask,
    float* __restrict__ attn_out) {
    const int h = blockIdx.x;
    const int b = blockIdx.y;
    const int tid = threadIdx.x;
    __shared__ float red[256];

    const int* mrow = mask + (size_t)b * TT;
    const size_t orow = ((size_t)(b * HH + h)) * TT;

    float sloc[16];
    float lmax = -3.0e38f;
#pragma unroll
    for (int it = 0; it < 16; it++) {
        const int t = tid + it * 256;
        const float s = scores[orow + t];
        const float ms = (mrow[t] > 0) ? s : -1e30f;
        sloc[it] = ms;
        lmax = fmaxf(lmax, ms);
    }
    red[tid] = lmax;
    __syncthreads();
    for (int st = 128; st > 0; st >>= 1) {
        if (tid < st) red[tid] = fmaxf(red[tid], red[tid + st]);
        __syncthreads();
    }
    const float mx = red[0];
    __syncthreads();

    float lsum = 0.f;
#pragma unroll
    for (int it = 0; it < 16; it++) {
        const float e = __expf(sloc[it] - mx);
        sloc[it] = e;
        lsum += e;
    }
    red[tid] = lsum;
    __syncthreads();
    for (int st = 128; st > 0; st >>= 1) {
        if (tid < st) red[tid] += red[tid + st];
        __syncthreads();
    }
    const float inv = 1.0f / red[0];
#pragma unroll
    for (int it = 0; it < 16; it++)
        attn_out[orow + tid + it * 256] = sloc[it] * inv;
}

// ---------------------------------------------------------------------------
// r via mma.sync tf32: per b, r[16,1024] = attn[16,4096] @ matrix[4096,1024]
// grid = (16 n-tiles of 64, 32 b), block = 256 (8 warps x 8-col n-tiles)
// Kc=64, 2-stage, 1 barrier/chunk, register prefetch, on-the-fly rounding.
// ---------------------------------------------------------------------------
#define RM_BSTRIDE 72
#define RM_ASTRIDE 68
__global__ __launch_bounds__(256) void rmix_kernel(
    const float* __restrict__ attn, const float* __restrict__ matrix,
    float* __restrict__ r) {
    __shared__ float Bst[2][64 * RM_BSTRIDE];
    __shared__ float Ast[2][16 * RM_ASTRIDE];
    const int tid = threadIdx.x;
    const int wid = tid >> 5;
    const int lid = tid & 31;
    const int g = lid >> 2, tig = lid & 3;
    const int n0 = blockIdx.x * 64;
    const int b = blockIdx.y;
    const int wn = wid * 8;

    float acc[4];
#pragma unroll
    for (int q = 0; q < 4; q++) acc[q] = 0.f;

    const float4* mat4 = (const float4*)matrix;
    const float4* attn4 = (const float4*)(attn + ((size_t)b * HH) * TT);
    float4 preB[4];
    float4 preA;
    const int ha = tid >> 4, cua = tid & 15;

    auto ldgChunk = [&](int c) {
        const int k0 = c * 64;
#pragma unroll
        for (int j = 0; j < 4; j++) {
            const int u = tid + j * 256;
            const int kr = u >> 4, cu = u & 15;
            preB[j] = mat4[(size_t)(b * TT + k0 + kr) * 256 + (n0 >> 2) + cu];
        }
        preA = attn4[(size_t)ha * (TT / 4) + (k0 >> 2) + cua];
    };
    auto stsChunk = [&](int s) {
#pragma unroll
        for (int j = 0; j < 4; j++) {
            const int u = tid + j * 256;
            const int kr = u >> 4, cu = u & 15;
            *(float4*)(&Bst[s][kr * RM_BSTRIDE + cu * 4]) = cvt4(preB[j]);
        }
        *(float4*)(&Ast[s][ha * RM_ASTRIDE + cua * 4]) = cvt4(preA);
    };

    // Prologue
    ldgChunk(0);
    stsChunk(0);
    ldgChunk(1);
    __syncthreads();

    for (int c = 0; c < 64; c++) {
        const int s = c & 1;
        if (c < 63) stsChunk(s ^ 1);
        if (c < 62) ldgChunk(c + 2);
        const float* As_s = Ast[s];
        const float* Bs_s = Bst[s];
#pragma unroll
        for (int ks = 0; ks < 8; ks++) {
            const int kb = ks * 8;
            const uint32_t a0 = __float_as_uint(As_s[(g) * RM_ASTRIDE + kb + tig]);
            const uint32_t a1 = __float_as_uint(As_s[(g + 8) * RM_ASTRIDE + kb + tig]);
            const uint32_t a2 = __float_as_uint(As_s[(g) * RM_ASTRIDE + kb + tig + 4]);
            const uint32_t a3 = __float_as_uint(As_s[(g + 8) * RM_ASTRIDE + kb + tig + 4]);
            const int nc = wn + g;
            const uint32_t b0 = __float_as_uint(Bs_s[(kb + tig) * RM_BSTRIDE + nc]);
            const uint32_t b1 = __float_as_uint(Bs_s[(kb + tig + 4) * RM_BSTRIDE + nc]);
            mma_tf32(acc, a0, a1, a2, a3, b0, b1);
        }
        __syncthreads();
    }

    // Epilogue: r[b][h][i]
    const int i = n0 + wn + 2 * tig;
    float2 lo = {acc[0], acc[1]};
    float2 hi = {acc[2], acc[3]};
    *(float2*)(r + ((size_t)(b * HH + g)) * DD + i) = lo;
    *(float2*)(r + ((size_t)(b * HH + g + 8)) * DD + i) = hi;
}

// ---------------------------------------------------------------------------
// ctx[b][hd] = sum_i r[b][hd>>6][i] * Wv[i][hd] + bv[hd]
// ---------------------------------------------------------------------------
__global__ __launch_bounds__(256) void ctx_kernel(
    const float* __restrict__ r, const float* __restrict__ Wv,
    const float* __restrict__ bv, float* __restrict__ ctx) {
    __shared__ float r_s[4 * DD];
    const int tid = threadIdx.x;
    const int hd = blockIdx.x * 256 + tid;
    const int b = blockIdx.y;
    const int h0 = (blockIdx.x * 256) >> 6;

    {
        const float4* src = (const float4*)(r + ((size_t)(b * HH + h0)) * DD);
        float4* dst = (float4*)r_s;
#pragma unroll
        for (int j = 0; j < 4; j++) dst[tid + j * 256] = src[tid + j * 256];
    }
    __syncthreads();

    const float* rr = r_s + ((hd >> 6) - h0) * DD;
    float acc = 0.f;
#pragma unroll 8
    for (int i = 0; i < DD; i++) acc += rr[i] * Wv[(size_t)i * DD + hd];
    ctx[(size_t)b * DD + hd] = acc + bv[hd];
}

// ---------------------------------------------------------------------------
// Launch
// ---------------------------------------------------------------------------
extern "C" void kernel_launch(void* const* d_in, const int* in_sizes, int n_in,
                              void* d_out, int out_size) {
    const float* vector = (const float*)d_in[0];
    const float* matrix = (const float*)d_in[1];
    const int*   mask   = (const int*)d_in[2];
    const float* Wq = (const float*)d_in[3];
    const float* bq = (const float*)d_in[4];
    const float* Wk = (const float*)d_in[5];
    const float* bk = (const float*)d_in[6];
    const float* Wv = (const float*)d_in[7];
    const float* bv = (const float*)d_in[8];
    const float* Wo = (const float*)d_in[9];
    const float* bo = (const float*)d_in[10];

    float* out = (float*)d_out;
    float* out_final  = out;
    float* attn_out   = out + (size_t)BB * DD;
    float* scores_out = attn_out + (size_t)BB * HH * TT;

    float *pq, *pwqt, *psb, *pr, *pctx, *ppp;
    cudaGetSymbolAddress((void**)&pq, g_q);
    cudaGetSymbolAddress((void**)&pwqt, g_wqt);
    cudaGetSymbolAddress((void**)&psb, g_sb);
    cudaGetSymbolAddress((void**)&pr, g_r);
    cudaGetSymbolAddress((void**)&pctx, g_ctx);
    cudaGetSymbolAddress((void**)&ppp, g_pp);

    cudaFuncSetAttribute(wqt_kernel,
                         cudaFuncAttributeMaxDynamicSharedMemorySize, WQT_SMEM);

    // q = vector @ Wq + bq (split-k)
    dim3 rpgrid(4, BB);
    rp_part_kernel<<<rpgrid, 256>>>(vector, Wq, ppp);
    rp_reduce_kernel<<<BB, 256>>>(ppp, bq, pq);

    // wq~ and sb
    dim3 wgrid(4, BB);
    wqt_kernel<<<wgrid, 256, WQT_SMEM>>>(Wk, pq, pwqt);
    sb_kernel<<<BB, 512>>>(bk, pq, psb);

    // scores = matrix @ wq~ + sb  (tf32 mma, pipelined)
    dim3 sgrid(16, BB);
    scores_mma_kernel<<<sgrid, 256>>>(matrix, pwqt, psb, scores_out);

    // attn = masked softmax(scores)
    dim3 smgrid(HH, BB);
    softmax_kernel<<<smgrid, 256>>>(scores_out, mask, attn_out);

    // r = attn @ matrix (tf32 mma, pipelined)
    dim3 rgrid(16, BB);
    rmix_kernel<<<rgrid, 256>>>(attn_out, matrix, pr);

    // ctx = r @ Wv + bv
    dim3 cgrid(4, BB);
    ctx_kernel<<<cgrid, 256>>>(pr, Wv, bv, pctx);

    // out = ctx @ Wo + bo (split-k)
    rp_part_kernel<<<rpgrid, 256>>>(pctx, Wo, ppp);
    rp_reduce_kernel<<<BB, 256>>>(ppp, bo, out_final);
}

// round 11
// speedup vs baseline: 25.8620x; 1.1194x over previous
#include <cuda_runtime.h>
#include <math.h>
#include <stdint.h>

#define BB 32
#define TT 4096
#define DD 1024
#define HH 16
#define DHEAD 64

// Scratch (device globals; no allocations)
__device__ float g_q[BB * DD];
__device__ float g_wqt[BB * HH * DD];   // wq~[b][h][i], tf32-rounded, incl /8
__device__ float g_sb[BB * HH];
__device__ float g_r[BB * HH * DD];     // r[b][h][i]
__device__ float g_ctx[BB * DD];
__device__ float g_pp[BB * 4 * DD];     // rowproj partials

// ---------------------------------------------------------------------------
__device__ __forceinline__ uint32_t f2tf32(float x) {
    uint32_t u;
    asm("cvt.rna.tf32.f32 %0, %1;" : "=r"(u) : "f"(x));
    return u;
}
__device__ __forceinline__ uint32_t smem_u32(const void* p) {
    uint32_t a;
    asm("{ .reg .u64 t; cvta.to.shared.u64 t, %1; cvt.u32.u64 %0, t; }"
        : "=r"(a) : "l"(p));
    return a;
}
__device__ __forceinline__ void cp_async16(uint32_t sdst, const void* gsrc) {
    asm volatile("cp.async.cg.shared.global [%0], [%1], 16;" :: "r"(sdst), "l"(gsrc));
}
#define CP_COMMIT() asm volatile("cp.async.commit_group;" ::: "memory")
#define CP_WAIT(n)  asm volatile("cp.async.wait_group %0;" :: "n"(n) : "memory")

__device__ __forceinline__ void mma_tf32(
    float* c, uint32_t a0, uint32_t a1, uint32_t a2, uint32_t a3,
    uint32_t b0, uint32_t b1) {
    asm volatile(
        "mma.sync.aligned.m16n8k8.row.col.f32.tf32.tf32.f32 "
        "{%0,%1,%2,%3}, {%4,%5,%6,%7}, {%8,%9}, {%0,%1,%2,%3};"
        : "+f"(c[0]), "+f"(c[1]), "+f"(c[2]), "+f"(c[3])
        : "r"(a0), "r"(a1), "r"(a2), "r"(a3), "r"(b0), "r"(b1));
}

// ---------------------------------------------------------------------------
// Split row projection: partials over k-slices of 256, then reduce.
// ---------------------------------------------------------------------------
__global__ __launch_bounds__(256) void rp_part_kernel(
    const float* __restrict__ X, const float* __restrict__ W,
    float* __restrict__ pp) {
    __shared__ float xs[256];
    const int s = blockIdx.x;
    const int b = blockIdx.y;
    const int tid = threadIdx.x;
    xs[tid] = X[(size_t)b * DD + s * 256 + tid];
    __syncthreads();
    float a0 = 0.f, a1 = 0.f, a2 = 0.f, a3 = 0.f;
#pragma unroll 8
    for (int k = 0; k < 256; k++) {
        const float xv = xs[k];
        const float* wr = W + (size_t)(s * 256 + k) * DD;
        a0 += xv * wr[tid];
        a1 += xv * wr[tid + 256];
        a2 += xv * wr[tid + 512];
        a3 += xv * wr[tid + 768];
    }
    float* o = pp + (size_t)(b * 4 + s) * DD;
    o[tid] = a0; o[tid + 256] = a1; o[tid + 512] = a2; o[tid + 768] = a3;
}

__global__ __launch_bounds__(256) void rp_reduce_kernel(
    const float* __restrict__ pp, const float* __restrict__ bias,
    float* __restrict__ Y) {
    const int b = blockIdx.x;
    const int tid = threadIdx.x;
#pragma unroll
    for (int j = 0; j < 4; j++) {
        const int c = tid + j * 256;
        float s = bias[c];
#pragma unroll
        for (int sl = 0; sl < 4; sl++) s += pp[(size_t)(b * 4 + sl) * DD + c];
        Y[(size_t)b * DD + c] = s;
    }
}

// ---------------------------------------------------------------------------
// wq~[b][h][i] = tf32( (1/8) * sum_d Wk[i][h*64+d] * q[b][h*64+d] )
// ---------------------------------------------------------------------------
#define WQT_SMEM ((256 * 65 + 64) * 4)
__global__ __launch_bounds__(256) void wqt_kernel(
    const float* __restrict__ Wk, const float* __restrict__ q,
    float* __restrict__ wqt) {
    extern __shared__ float sm[];
    float* wk_s = sm;
    float* q_s  = sm + 256 * 65;
    const int tid = threadIdx.x;
    const int i0 = blockIdx.x * 256;
    const int b = blockIdx.y;

    float acc[HH];
#pragma unroll 1
    for (int h = 0; h < HH; h++) {
        __syncthreads();
        if (tid < 16)
            ((float4*)q_s)[tid] =
                ((const float4*)(q + (size_t)b * DD + h * DHEAD))[tid];
#pragma unroll
        for (int j = 0; j < 16; j++) {
            const int u = tid + j * 256;
            const int row = u >> 4, i4 = u & 15;
            float4 v = ((const float4*)Wk)[(size_t)(i0 + row) * 256 + h * 16 + i4];
            float* d = wk_s + row * 65 + i4 * 4;
            d[0] = v.x; d[1] = v.y; d[2] = v.z; d[3] = v.w;
        }
        __syncthreads();
        float s = 0.f;
        const float* wr = wk_s + tid * 65;
#pragma unroll 8
        for (int dd = 0; dd < 64; dd++) s += wr[dd] * q_s[dd];
        acc[h] = s * 0.125f;
    }
#pragma unroll
    for (int h = 0; h < HH; h++)
        wqt[((size_t)(b * HH + h)) * DD + i0 + tid] =
            __uint_as_float(f2tf32(acc[h]));
}

// ---------------------------------------------------------------------------
// sb[b][h] = (1/8) * bk[h,:].q^[b,h,:]
// ---------------------------------------------------------------------------
__global__ __launch_bounds__(512) void sb_kernel(
    const float* __restrict__ bk, const float* __restrict__ q,
    float* __restrict__ sb) {
    const int b = blockIdx.x;
    const int h = threadIdx.x >> 5;
    const int lane = threadIdx.x & 31;
    const int hd = h * DHEAD + lane * 2;
    float s = bk[hd] * q[b * DD + hd] + bk[hd + 1] * q[b * DD + hd + 1];
#pragma unroll
    for (int o = 16; o > 0; o >>= 1)
        s += __shfl_down_sync(0xFFFFFFFF, s, o);
    if (lane == 0) sb[b * HH + h] = s * 0.125f;
}

// ---------------------------------------------------------------------------
// scores via mma.sync tf32: per b, C[4096,16] = matrix[4096,1024] @ wq~T
// grid = (16 t-tiles of 256, 32 b), block = 256.
// 3-stage cp.async ring (wait_group 2 => >=2 chunks of latency slack).
// matrix staged raw fp32; cvt.rna.tf32 applied at LDS time in math phase.
// ---------------------------------------------------------------------------
#define SC_STRIDE 20
#define SC_AS_FLOATS (256 * SC_STRIDE)
#define SC_BS_FLOATS (16 * SC_STRIDE)
#define SC_SMEM ((3 * SC_AS_FLOATS + 3 * SC_BS_FLOATS) * 4)   // 65280 B
__global__ __launch_bounds__(256, 3) void scores_mma_kernel(
    const float* __restrict__ matrix, const float* __restrict__ wqt,
    const float* __restrict__ sb, float* __restrict__ scores_out) {
    extern __shared__ float smx[];
    float* As[3] = {smx, smx + SC_AS_FLOATS, smx + 2 * SC_AS_FLOATS};
    float* Bsb = smx + 3 * SC_AS_FLOATS;
    float* Bs[3] = {Bsb, Bsb + SC_BS_FLOATS, Bsb + 2 * SC_BS_FLOATS};
    const uint32_t asu0 = smem_u32(As[0]);
    const uint32_t bsu0 = smem_u32(Bs[0]);

    const int tid = threadIdx.x;
    const int wid = tid >> 5;
    const int lid = tid & 31;
    const int g = lid >> 2, tig = lid & 3;
    const int t0 = blockIdx.x * 256;
    const int b = blockIdx.y;
    const int wm = wid * 32;

    const char* matbase = (const char*)(matrix + (size_t)(b * TT + t0) * DD);
    const char* wqb = (const char*)(wqt + (size_t)b * HH * DD);

    // issue chunk c into stage s (A: 4 copies/thread; B: 1 copy for tid<64)
    auto issueChunk = [&](int c, int s) {
        const uint32_t au = asu0 + (uint32_t)s * (SC_AS_FLOATS * 4);
#pragma unroll
        for (int j = 0; j < 4; j++) {
            const int u = tid + j * 256;
            const int r = u >> 2, cu = u & 3;
            cp_async16(au + (uint32_t)(r * (SC_STRIDE * 4) + cu * 16),
                       matbase + (size_t)r * (DD * 4) + c * 64 + cu * 16);
        }
        if (tid < 64) {
            const int h = tid >> 2, k4 = tid & 3;
            cp_async16(bsu0 + (uint32_t)s * (SC_BS_FLOATS * 4) +
                           (uint32_t)(h * (SC_STRIDE * 4) + k4 * 16),
                       wqb + (size_t)h * (DD * 4) + c * 64 + k4 * 16);
        }
        CP_COMMIT();
    };

    float acc[2][2][4];
#pragma unroll
    for (int i = 0; i < 2; i++)
#pragma unroll
        for (int j = 0; j < 2; j++)
#pragma unroll
            for (int q = 0; q < 4; q++) acc[i][j][q] = 0.f;

    issueChunk(0, 0);
    issueChunk(1, 1);
    issueChunk(2, 2);

    for (int c = 0; c < 64; c++) {
        const int s = c % 3;
        CP_WAIT(2);
        __syncthreads();
        const float* As_s = As[s];
        const float* Bs_s = Bs[s];
#pragma unroll
        for (int ks = 0; ks < 2; ks++) {
            const int kb = ks * 8;
            uint32_t af[2][4];
#pragma unroll
            for (int mf = 0; mf < 2; mf++) {
                const int rb = wm + mf * 16;
                af[mf][0] = f2tf32(As_s[(rb + g) * SC_STRIDE + kb + tig]);
                af[mf][1] = f2tf32(As_s[(rb + g + 8) * SC_STRIDE + kb + tig]);
                af[mf][2] = f2tf32(As_s[(rb + g) * SC_STRIDE + kb + tig + 4]);
                af[mf][3] = f2tf32(As_s[(rb + g + 8) * SC_STRIDE + kb + tig + 4]);
            }
#pragma unroll
            for (int nf = 0; nf < 2; nf++) {
                const int nb = nf * 8;
                const uint32_t b0 = __float_as_uint(Bs_s[(nb + g) * SC_STRIDE + kb + tig]);
                const uint32_t b1 = __float_as_uint(Bs_s[(nb + g) * SC_STRIDE + kb + tig + 4]);
#pragma unroll
                for (int mf = 0; mf < 2; mf++)
                    mma_tf32(acc[mf][nf], af[mf][0], af[mf][1], af[mf][2],
                             af[mf][3], b0, b1);
            }
        }
        __syncthreads();
        if (c + 3 < 64) issueChunk(c + 3, s);
        else CP_COMMIT();   // keep per-thread group counts aligned
    }

    // Epilogue
#pragma unroll
    for (int mf = 0; mf < 2; mf++) {
        const int t_lo = t0 + wm + mf * 16 + g;
#pragma unroll
        for (int nf = 0; nf < 2; nf++) {
            const int h0 = nf * 8 + 2 * tig;
            const float s0 = sb[b * HH + h0];
            const float s1 = sb[b * HH + h0 + 1];
            scores_out[((size_t)(b * HH + h0)) * TT + t_lo] = acc[mf][nf][0] + s0;
            scores_out[((size_t)(b * HH + h0 + 1)) * TT + t_lo] = acc[mf][nf][1] + s1;
            scores_out[((size_t)(b * HH + h0)) * TT + t_lo + 8] = acc[mf][nf][2] + s0;
            scores_out[((size_t)(b * HH + h0 + 1)) * TT + t_lo + 8] = acc[mf][nf][3] + s1;
        }
    }
}

// ---------------------------------------------------------------------------
// Masked softmax
// ---------------------------------------------------------------------------
__global__ __launch_bounds__(256) void softmax_kernel(
    const float* __restrict__ scores, const int* __restrict__ mask,
    float* __restrict__ attn_out) {
    const int h = blockIdx.x;
    const int b = blockIdx.y;
    const int tid = threadIdx.x;
    __shared__ float red[256];

    const int* mrow = mask + (size_t)b * TT;
    const size_t orow = ((size_t)(b * HH + h)) * TT;

    float sloc[16];
    float lmax = -3.0e38f;
#pragma unroll
    for (int it = 0; it < 16; it++) {
        const int t = tid + it * 256;
        const float s = scores[orow + t];
        const float ms = (mrow[t] > 0) ? s : -1e30f;
        sloc[it] = ms;
        lmax = fmaxf(lmax, ms);
    }
    red[tid] = lmax;
    __syncthreads();
    for (int st = 128; st > 0; st >>= 1) {
        if (tid < st) red[tid] = fmaxf(red[tid], red[tid + st]);
        __syncthreads();
    }
    const float mx = red[0];
    __syncthreads();

    float lsum = 0.f;
#pragma unroll
    for (int it = 0; it < 16; it++) {
        const float e = __expf(sloc[it] - mx);
        sloc[it] = e;
        lsum += e;
    }
    red[tid] = lsum;
    __syncthreads();
    for (int st = 128; st > 0; st >>= 1) {
        if (tid < st) red[tid] += red[tid + st];
        __syncthreads();
    }
    const float inv = 1.0f / red[0];
#pragma unroll
    for (int it = 0; it < 16; it++)
        attn_out[orow + tid + it * 256] = sloc[it] * inv;
}

// ---------------------------------------------------------------------------
// r via mma.sync tf32: per b, r[16,1024] = attn[16,4096] @ matrix[4096,1024]
// grid = (16 n-tiles of 64, 32 b), block = 256; Kc=64.
// 3-stage cp.async ring; cvt.rna at LDS time.
// ---------------------------------------------------------------------------
#define RM_BSTRIDE 72
#define RM_ASTRIDE 68
#define RM_BS_FLOATS (64 * RM_BSTRIDE)
#define RM_AS_FLOATS (16 * RM_ASTRIDE)
#define RM_SMEM ((3 * RM_BS_FLOATS + 3 * RM_AS_FLOATS) * 4)   // 68352 B
__global__ __launch_bounds__(256, 3) void rmix_kernel(
    const float* __restrict__ attn, const float* __restrict__ matrix,
    float* __restrict__ r) {
    extern __shared__ float smx[];
    float* Bst[3] = {smx, smx + RM_BS_FLOATS, smx + 2 * RM_BS_FLOATS};
    float* Asb = smx + 3 * RM_BS_FLOATS;
    float* Ast[3] = {Asb, Asb + RM_AS_FLOATS, Asb + 2 * RM_AS_FLOATS};
    const uint32_t bsu0 = smem_u32(Bst[0]);
    const uint32_t asu0 = smem_u32(Ast[0]);

    const int tid = threadIdx.x;
    const int wid = tid >> 5;
    const int lid = tid & 31;
    const int g = lid >> 2, tig = lid & 3;
    const int n0 = blockIdx.x * 64;
    const int b = blockIdx.y;
    const int wn = wid * 8;

    float acc[4];
#pragma unroll
    for (int q = 0; q < 4; q++) acc[q] = 0.f;

    const char* matbase = (const char*)(matrix + (size_t)b * TT * DD + n0);
    const char* attnbase = (const char*)(attn + (size_t)b * HH * TT);
    const int ha = tid >> 4, cua = tid & 15;

    auto issueChunk = [&](int c, int s) {
        const int k0 = c * 64;
        const uint32_t bu = bsu0 + (uint32_t)s * (RM_BS_FLOATS * 4);
#pragma unroll
        for (int j = 0; j < 4; j++) {
            const int u = tid + j * 256;
            const int kr = u >> 4, cu = u & 15;
            cp_async16(bu + (uint32_t)(kr * (RM_BSTRIDE * 4) + cu * 16),
                       matbase + (size_t)(k0 + kr) * (DD * 4) + cu * 16);
        }
        cp_async16(asu0 + (uint32_t)s * (RM_AS_FLOATS * 4) +
                       (uint32_t)(ha * (RM_ASTRIDE * 4) + cua * 16),
                   attnbase + (size_t)ha * (TT * 4) + k0 * 4 + cua * 16);
        CP_COMMIT();
    };

    issueChunk(0, 0);
    issueChunk(1, 1);
    issueChunk(2, 2);

    for (int c = 0; c < 64; c++) {
        const int s = c % 3;
        CP_WAIT(2);
        __syncthreads();
        const float* As_s = Ast[s];
        const float* Bs_s = Bst[s];
#pragma unroll
        for (int ks = 0; ks < 8; ks++) {
            const int kb = ks * 8;
            const uint32_t a0 = f2tf32(As_s[(g) * RM_ASTRIDE + kb + tig]);
            const uint32_t a1 = f2tf32(As_s[(g + 8) * RM_ASTRIDE + kb + tig]);
            const uint32_t a2 = f2tf32(As_s[(g) * RM_ASTRIDE + kb + tig + 4]);
            const uint32_t a3 = f2tf32(As_s[(g + 8) * RM_ASTRIDE + kb + tig + 4]);
            const int nc = wn + g;
            const uint32_t b0 = f2tf32(Bs_s[(kb + tig) * RM_BSTRIDE + nc]);
            const uint32_t b1 = f2tf32(Bs_s[(kb + tig + 4) * RM_BSTRIDE + nc]);
            mma_tf32(acc, a0, a1, a2, a3, b0, b1);
        }
        __syncthreads();
        if (c + 3 < 64) issueChunk(c + 3, s);
        else CP_COMMIT();
    }

    // Epilogue: r[b][h][i]
    const int i = n0 + wn + 2 * tig;
    float2 lo = {acc[0], acc[1]};
    float2 hi = {acc[2], acc[3]};
    *(float2*)(r + ((size_t)(b * HH + g)) * DD + i) = lo;
    *(float2*)(r + ((size_t)(b * HH + g + 8)) * DD + i) = hi;
}

// ---------------------------------------------------------------------------
// ctx[b][hd] = sum_i r[b][hd>>6][i] * Wv[i][hd] + bv[hd]
// ---------------------------------------------------------------------------
__global__ __launch_bounds__(256) void ctx_kernel(
    const float* __restrict__ r, const float* __restrict__ Wv,
    const float* __restrict__ bv, float* __restrict__ ctx) {
    __shared__ float r_s[4 * DD];
    const int tid = threadIdx.x;
    const int hd = blockIdx.x * 256 + tid;
    const int b = blockIdx.y;
    const int h0 = (blockIdx.x * 256) >> 6;

    {
        const float4* src = (const float4*)(r + ((size_t)(b * HH + h0)) * DD);
        float4* dst = (float4*)r_s;
#pragma unroll
        for (int j = 0; j < 4; j++) dst[tid + j * 256] = src[tid + j * 256];
    }
    __syncthreads();

    const float* rr = r_s + ((hd >> 6) - h0) * DD;
    float acc = 0.f;
#pragma unroll 16
    for (int i = 0; i < DD; i++) acc += rr[i] * Wv[(size_t)i * DD + hd];
    ctx[(size_t)b * DD + hd] = acc + bv[hd];
}

// ---------------------------------------------------------------------------
// Launch
// ---------------------------------------------------------------------------
extern "C" void kernel_launch(void* const* d_in, const int* in_sizes, int n_in,
                              void* d_out, int out_size) {
    const float* vector = (const float*)d_in[0];
    const float* matrix = (const float*)d_in[1];
    const int*   mask   = (const int*)d_in[2];
    const float* Wq = (const float*)d_in[3];
    const float* bq = (const float*)d_in[4];
    const float* Wk = (const float*)d_in[5];
    const float* bk = (const float*)d_in[6];
    const float* Wv = (const float*)d_in[7];
    const float* bv = (const float*)d_in[8];
    const float* Wo = (const float*)d_in[9];
    const float* bo = (const float*)d_in[10];

    float* out = (float*)d_out;
    float* out_final  = out;
    float* attn_out   = out + (size_t)BB * DD;
    float* scores_out = attn_out + (size_t)BB * HH * TT;

    float *pq, *pwqt, *psb, *pr, *pctx, *ppp;
    cudaGetSymbolAddress((void**)&pq, g_q);
    cudaGetSymbolAddress((void**)&pwqt, g_wqt);
    cudaGetSymbolAddress((void**)&psb, g_sb);
    cudaGetSymbolAddress((void**)&pr, g_r);
    cudaGetSymbolAddress((void**)&pctx, g_ctx);
    cudaGetSymbolAddress((void**)&ppp, g_pp);

    cudaFuncSetAttribute(wqt_kernel,
                         cudaFuncAttributeMaxDynamicSharedMemorySize, WQT_SMEM);
    cudaFuncSetAttribute(scores_mma_kernel,
                         cudaFuncAttributeMaxDynamicSharedMemorySize, SC_SMEM);
    cudaFuncSetAttribute(rmix_kernel,
                         cudaFuncAttributeMaxDynamicSharedMemorySize, RM_SMEM);

    // q = vector @ Wq + bq (split-k)
    dim3 rpgrid(4, BB);
    rp_part_kernel<<<rpgrid, 256>>>(vector, Wq, ppp);
    rp_reduce_kernel<<<BB, 256>>>(ppp, bq, pq);

    // wq~ and sb
    dim3 wgrid(4, BB);
    wqt_kernel<<<wgrid, 256, WQT_SMEM>>>(Wk, pq, pwqt);
    sb_kernel<<<BB, 512>>>(bk, pq, psb);

    // scores = matrix @ wq~ + sb  (tf32 mma, cp.async 3-stage)
    dim3 sgrid(16, BB);
    scores_mma_kernel<<<sgrid, 256, SC_SMEM>>>(matrix, pwqt, psb, scores_out);

    // attn = masked softmax(scores)
    dim3 smgrid(HH, BB);
    softmax_kernel<<<smgrid, 256>>>(scores_out, mask, attn_out);

    // r = attn @ matrix (tf32 mma, cp.async 3-stage)
    dim3 rgrid(16, BB);
    rmix_kernel<<<rgrid, 256, RM_SMEM>>>(attn_out, matrix, pr);

    // ctx = r @ Wv + bv
    dim3 cgrid(4, BB);
    ctx_kernel<<<cgrid, 256>>>(pr, Wv, bv, pctx);

    // out = ctx @ Wo + bo (split-k)
    rp_part_kernel<<<rpgrid, 256>>>(pctx, Wo, ppp);
    rp_reduce_kernel<<<BB, 256>>>(ppp, bo, out_final);
}

// round 13
// speedup vs baseline: 26.5277x; 1.0257x over previous
#include <cuda_runtime.h>
#include <math.h>
#include <stdint.h>

#define BB 32
#define TT 4096
#define DD 1024
#define HH 16
#define DHEAD 64

// Scratch (device globals; no allocations)
__device__ float g_q[BB * DD];
__device__ float g_wqt[BB * HH * DD];   // wq~[b][h][i], tf32-rounded, incl /8
__device__ float g_sb[BB * HH];
__device__ float g_r[BB * HH * DD];     // r[b][h][i]
__device__ float g_ctx[BB * DD];
__device__ float g_pp[BB * 4 * DD];     // rowproj partials

// ---------------------------------------------------------------------------
__device__ __forceinline__ uint32_t f2tf32(float x) {
    uint32_t u;
    asm("cvt.rna.tf32.f32 %0, %1;" : "=r"(u) : "f"(x));
    return u;
}
__device__ __forceinline__ uint32_t smem_u32(const void* p) {
    uint32_t a;
    asm("{ .reg .u64 t; cvta.to.shared.u64 t, %1; cvt.u32.u64 %0, t; }"
        : "=r"(a) : "l"(p));
    return a;
}
__device__ __forceinline__ void cp_async16(uint32_t sdst, const void* gsrc) {
    asm volatile("cp.async.cg.shared.global [%0], [%1], 16;" :: "r"(sdst), "l"(gsrc));
}
#define CP_COMMIT() asm volatile("cp.async.commit_group;" ::: "memory")
#define CP_WAIT(n)  asm volatile("cp.async.wait_group %0;" :: "n"(n) : "memory")

__device__ __forceinline__ void mma_tf32(
    float* c, uint32_t a0, uint32_t a1, uint32_t a2, uint32_t a3,
    uint32_t b0, uint32_t b1) {
    asm volatile(
        "mma.sync.aligned.m16n8k8.row.col.f32.tf32.tf32.f32 "
        "{%0,%1,%2,%3}, {%4,%5,%6,%7}, {%8,%9}, {%0,%1,%2,%3};"
        : "+f"(c[0]), "+f"(c[1]), "+f"(c[2]), "+f"(c[3])
        : "r"(a0), "r"(a1), "r"(a2), "r"(a3), "r"(b0), "r"(b1));
}

// ---------------------------------------------------------------------------
// Split row projection: partials over k-slices of 256, then reduce.
// ---------------------------------------------------------------------------
__global__ __launch_bounds__(256) void rp_part_kernel(
    const float* __restrict__ X, const float* __restrict__ W,
    float* __restrict__ pp) {
    __shared__ float xs[256];
    const int s = blockIdx.x;
    const int b = blockIdx.y;
    const int tid = threadIdx.x;
    xs[tid] = X[(size_t)b * DD + s * 256 + tid];
    __syncthreads();
    float a0 = 0.f, a1 = 0.f, a2 = 0.f, a3 = 0.f;
#pragma unroll 8
    for (int k = 0; k < 256; k++) {
        const float xv = xs[k];
        const float* wr = W + (size_t)(s * 256 + k) * DD;
        a0 += xv * wr[tid];
        a1 += xv * wr[tid + 256];
        a2 += xv * wr[tid + 512];
        a3 += xv * wr[tid + 768];
    }
    float* o = pp + (size_t)(b * 4 + s) * DD;
    o[tid] = a0; o[tid + 256] = a1; o[tid + 512] = a2; o[tid + 768] = a3;
}

__global__ __launch_bounds__(256) void rp_reduce_kernel(
    const float* __restrict__ pp, const float* __restrict__ bias,
    float* __restrict__ Y) {
    const int b = blockIdx.x;
    const int tid = threadIdx.x;
#pragma unroll
    for (int j = 0; j < 4; j++) {
        const int c = tid + j * 256;
        float s = bias[c];
#pragma unroll
        for (int sl = 0; sl < 4; sl++) s += pp[(size_t)(b * 4 + sl) * DD + c];
        Y[(size_t)b * DD + c] = s;
    }
}

// ---------------------------------------------------------------------------
// wq~[b][h][i] = tf32( (1/8) * sum_d Wk[i][h*64+d] * q[b][h*64+d] )
// ---------------------------------------------------------------------------
#define WQT_SMEM ((256 * 65 + 64) * 4)
__global__ __launch_bounds__(256) void wqt_kernel(
    const float* __restrict__ Wk, const float* __restrict__ q,
    float* __restrict__ wqt) {
    extern __shared__ float sm[];
    float* wk_s = sm;
    float* q_s  = sm + 256 * 65;
    const int tid = threadIdx.x;
    const int i0 = blockIdx.x * 256;
    const int b = blockIdx.y;

    float acc[HH];
#pragma unroll 1
    for (int h = 0; h < HH; h++) {
        __syncthreads();
        if (tid < 16)
            ((float4*)q_s)[tid] =
                ((const float4*)(q + (size_t)b * DD + h * DHEAD))[tid];
#pragma unroll
        for (int j = 0; j < 16; j++) {
            const int u = tid + j * 256;
            const int row = u >> 4, i4 = u & 15;
            float4 v = ((const float4*)Wk)[(size_t)(i0 + row) * 256 + h * 16 + i4];
            float* d = wk_s + row * 65 + i4 * 4;
            d[0] = v.x; d[1] = v.y; d[2] = v.z; d[3] = v.w;
        }
        __syncthreads();
        float s = 0.f;
        const float* wr = wk_s + tid * 65;
#pragma unroll 8
        for (int dd = 0; dd < 64; dd++) s += wr[dd] * q_s[dd];
        acc[h] = s * 0.125f;
    }
#pragma unroll
    for (int h = 0; h < HH; h++)
        wqt[((size_t)(b * HH + h)) * DD + i0 + tid] =
            __uint_as_float(f2tf32(acc[h]));
}

// ---------------------------------------------------------------------------
// sb[b][h] = (1/8) * bk[h,:].q^[b,h,:]
// ---------------------------------------------------------------------------
__global__ __launch_bounds__(512) void sb_kernel(
    const float* __restrict__ bk, const float* __restrict__ q,
    float* __restrict__ sb) {
    const int b = blockIdx.x;
    const int h = threadIdx.x >> 5;
    const int lane = threadIdx.x & 31;
    const int hd = h * DHEAD + lane * 2;
    float s = bk[hd] * q[b * DD + hd] + bk[hd + 1] * q[b * DD + hd + 1];
#pragma unroll
    for (int o = 16; o > 0; o >>= 1)
        s += __shfl_down_sync(0xFFFFFFFF, s, o);
    if (lane == 0) sb[b * HH + h] = s * 0.125f;
}

// ---------------------------------------------------------------------------
// scores via mma.sync tf32: per b, C[4096,16] = matrix[4096,1024] @ wq~T
// grid = (16 t-tiles of 256, 32 b), block = 256. Single resident wave:
// Kc=8, 4-stage cp.async ring, 52.2 KB smem -> 4 CTAs/SM (512 conc >= grid).
// cvt.rna.tf32 applied at LDS time.
// ---------------------------------------------------------------------------
#define SC_STRIDE 12
#define SC_AS_FLOATS (256 * SC_STRIDE)
#define SC_BS_FLOATS (16 * SC_STRIDE)
#define SC_STAGE_FLOATS (SC_AS_FLOATS + SC_BS_FLOATS)
#define SC_SMEM (4 * SC_STAGE_FLOATS * 4)   // 52224 B
__global__ __launch_bounds__(256, 4) void scores_mma_kernel(
    const float* __restrict__ matrix, const float* __restrict__ wqt,
    const float* __restrict__ sb, float* __restrict__ scores_out) {
    extern __shared__ float smx[];
    const uint32_t su0 = smem_u32(smx);

    const int tid = threadIdx.x;
    const int wid = tid >> 5;
    const int lid = tid & 31;
    const int g = lid >> 2, tig = lid & 3;
    const int t0 = blockIdx.x * 256;
    const int b = blockIdx.y;
    const int wm = wid * 32;

    const char* matbase = (const char*)(matrix + (size_t)(b * TT + t0) * DD);
    const char* wqb = (const char*)(wqt + (size_t)b * HH * DD);

    // issue chunk c (8 k-floats = 32 B) into stage s
    auto issueChunk = [&](int c, int s) {
        const uint32_t au = su0 + (uint32_t)(s * SC_STAGE_FLOATS * 4);
#pragma unroll
        for (int j = 0; j < 2; j++) {
            const int u = tid + j * 256;
            const int r = u >> 1, cu = u & 1;
            cp_async16(au + (uint32_t)(r * 48 + cu * 16),
                       matbase + (size_t)r * (DD * 4) + c * 32 + cu * 16);
        }
        if (tid < 32) {
            const int h = tid >> 1, k4 = tid & 1;
            cp_async16(au + (uint32_t)(SC_AS_FLOATS * 4) +
                           (uint32_t)(h * 48 + k4 * 16),
                       wqb + (size_t)h * (DD * 4) + c * 32 + k4 * 16);
        }
        CP_COMMIT();
    };

    float acc[2][2][4];
#pragma unroll
    for (int i = 0; i < 2; i++)
#pragma unroll
        for (int j = 0; j < 2; j++)
#pragma unroll
            for (int q = 0; q < 4; q++) acc[i][j][q] = 0.f;

    issueChunk(0, 0);
    issueChunk(1, 1);
    issueChunk(2, 2);
    issueChunk(3, 3);

    for (int c = 0; c < 128; c++) {
        const int s = c & 3;
        CP_WAIT(3);
        __syncthreads();
        const float* As_s = smx + s * SC_STAGE_FLOATS;
        const float* Bs_s = As_s + SC_AS_FLOATS;

        uint32_t af[2][4];
#pragma unroll
        for (int mf = 0; mf < 2; mf++) {
            const int rb = wm + mf * 16;
            af[mf][0] = f2tf32(As_s[(rb + g) * SC_STRIDE + tig]);
            af[mf][1] = f2tf32(As_s[(rb + g + 8) * SC_STRIDE + tig]);
            af[mf][2] = f2tf32(As_s[(rb + g) * SC_STRIDE + tig + 4]);
            af[mf][3] = f2tf32(As_s[(rb + g + 8) * SC_STRIDE + tig + 4]);
        }
#pragma unroll
        for (int nf = 0; nf < 2; nf++) {
            const int nb = nf * 8;
            const uint32_t b0 = __float_as_uint(Bs_s[(nb + g) * SC_STRIDE + tig]);
            const uint32_t b1 = __float_as_uint(Bs_s[(nb + g) * SC_STRIDE + tig + 4]);
#pragma unroll
            for (int mf = 0; mf < 2; mf++)
                mma_tf32(acc[mf][nf], af[mf][0], af[mf][1], af[mf][2],
                         af[mf][3], b0, b1);
        }
        __syncthreads();
        if (c + 4 < 128) issueChunk(c + 4, s);
        else CP_COMMIT();   // keep per-thread group counts aligned
    }

    // Epilogue
#pragma unroll
    for (int mf = 0; mf < 2; mf++) {
        const int t_lo = t0 + wm + mf * 16 + g;
#pragma unroll
        for (int nf = 0; nf < 2; nf++) {
            const int h0 = nf * 8 + 2 * tig;
            const float s0 = sb[b * HH + h0];
            const float s1 = sb[b * HH + h0 + 1];
            scores_out[((size_t)(b * HH + h0)) * TT + t_lo] = acc[mf][nf][0] + s0;
            scores_out[((size_t)(b * HH + h0 + 1)) * TT + t_lo] = acc[mf][nf][1] + s1;
            scores_out[((size_t)(b * HH + h0)) * TT + t_lo + 8] = acc[mf][nf][2] + s0;
            scores_out[((size_t)(b * HH + h0 + 1)) * TT + t_lo + 8] = acc[mf][nf][3] + s1;
        }
    }
}

// ---------------------------------------------------------------------------
// Masked softmax
// ---------------------------------------------------------------------------
__global__ __launch_bounds__(256) void softmax_kernel(
    const float* __restrict__ scores, const int* __restrict__ mask,
    float* __restrict__ attn_out) {
    const int h = blockIdx.x;
    const int b = blockIdx.y;
    const int tid = threadIdx.x;
    __shared__ float red[256];

    const int* mrow = mask + (size_t)b * TT;
    const size_t orow = ((size_t)(b * HH + h)) * TT;

    float sloc[16];
    float lmax = -3.0e38f;
#pragma unroll
    for (int it = 0; it < 16; it++) {
        const int t = tid + it * 256;
        const float s = scores[orow + t];
        const float ms = (mrow[t] > 0) ? s : -1e30f;
        sloc[it] = ms;
        lmax = fmaxf(lmax, ms);
    }
    red[tid] = lmax;
    __syncthreads();
    for (int st = 128; st > 0; st >>= 1) {
        if (tid < st) red[tid] = fmaxf(red[tid], red[tid + st]);
        __syncthreads();
    }
    const float mx = red[0];
    __syncthreads();

    float lsum = 0.f;
#pragma unroll
    for (int it = 0; it < 16; it++) {
        const float e = __expf(sloc[it] - mx);
        sloc[it] = e;
        lsum += e;
    }
    red[tid] = lsum;
    __syncthreads();
    for (int st = 128; st > 0; st >>= 1) {
        if (tid < st) red[tid] += red[tid + st];
        __syncthreads();
    }
    const float inv = 1.0f / red[0];
#pragma unroll
    for (int it = 0; it < 16; it++)
        attn_out[orow + tid + it * 256] = sloc[it] * inv;
}

// ---------------------------------------------------------------------------
// r via mma.sync tf32: per b, r[16,1024] = attn[16,4096] @ matrix[4096,1024]
// grid = (16 n-tiles of 64, 32 b), block = 256. Single resident wave:
// Kc=32, 4-stage cp.async ring, 46.1 KB smem -> 4 CTAs/SM.
// ---------------------------------------------------------------------------
#define RM_BSTRIDE 72
#define RM_ASTRIDE 36
#define RM_BS_FLOATS (32 * RM_BSTRIDE)
#define RM_AS_FLOATS (16 * RM_ASTRIDE)
#define RM_STAGE_FLOATS (RM_BS_FLOATS + RM_AS_FLOATS)
#define RM_SMEM (4 * RM_STAGE_FLOATS * 4)   // 46080 B
__global__ __launch_bounds__(256, 4) void rmix_kernel(
    const float* __restrict__ attn, const float* __restrict__ matrix,
    float* __restrict__ r) {
    extern __shared__ float smx[];
    const uint32_t su0 = smem_u32(smx);

    const int tid = threadIdx.x;
    const int wid = tid >> 5;
    const int lid = tid & 31;
    const int g = lid >> 2, tig = lid & 3;
    const int n0 = blockIdx.x * 64;
    const int b = blockIdx.y;
    const int wn = wid * 8;

    float acc[4];
#pragma unroll
    for (int q = 0; q < 4; q++) acc[q] = 0.f;

    const char* matbase = (const char*)(matrix + (size_t)b * TT * DD + n0);
    const char* attnbase = (const char*)(attn + (size_t)b * HH * TT);

    // issue chunk c (32 k-rows) into stage s
    auto issueChunk = [&](int c, int s) {
        const int k0 = c * 32;
        const uint32_t bu = su0 + (uint32_t)(s * RM_STAGE_FLOATS * 4);
#pragma unroll
        for (int j = 0; j < 2; j++) {
            const int u = tid + j * 256;
            const int kr = u >> 4, cu = u & 15;
            cp_async16(bu + (uint32_t)(kr * (RM_BSTRIDE * 4) + cu * 16),
                       matbase + (size_t)(k0 + kr) * (DD * 4) + cu * 16);
        }
        if (tid < 128) {
            const int ha = tid >> 3, cu = tid & 7;
            cp_async16(bu + (uint32_t)(RM_BS_FLOATS * 4) +
                           (uint32_t)(ha * (RM_ASTRIDE * 4) + cu * 16),
                       attnbase + (size_t)ha * (TT * 4) + k0 * 4 + cu * 16);
        }
        CP_COMMIT();
    };

    issueChunk(0, 0);
    issueChunk(1, 1);
    issueChunk(2, 2);
    issueChunk(3, 3);

    for (int c = 0; c < 128; c++) {
        const int s = c & 3;
        CP_WAIT(3);
        __syncthreads();
        const float* Bs_s = smx + s * RM_STAGE_FLOATS;
        const float* As_s = Bs_s + RM_BS_FLOATS;
#pragma unroll
        for (int ks = 0; ks < 4; ks++) {
            const int kb = ks * 8;
            const uint32_t a0 = f2tf32(As_s[(g) * RM_ASTRIDE + kb + tig]);
            const uint32_t a1 = f2tf32(As_s[(g + 8) * RM_ASTRIDE + kb + tig]);
            const uint32_t a2 = f2tf32(As_s[(g) * RM_ASTRIDE + kb + tig + 4]);
            const uint32_t a3 = f2tf32(As_s[(g + 8) * RM_ASTRIDE + kb + tig + 4]);
            const int nc = wn + g;
            const uint32_t b0 = f2tf32(Bs_s[(kb + tig) * RM_BSTRIDE + nc]);
            const uint32_t b1 = f2tf32(Bs_s[(kb + tig + 4) * RM_BSTRIDE + nc]);
            mma_tf32(acc, a0, a1, a2, a3, b0, b1);
        }
        __syncthreads();
        if (c + 4 < 128) issueChunk(c + 4, s);
        else CP_COMMIT();
    }

    // Epilogue: r[b][h][i]
    const int i = n0 + wn + 2 * tig;
    float2 lo = {acc[0], acc[1]};
    float2 hi = {acc[2], acc[3]};
    *(float2*)(r + ((size_t)(b * HH + g)) * DD + i) = lo;
    *(float2*)(r + ((size_t)(b * HH + g + 8)) * DD + i) = hi;
}

// ---------------------------------------------------------------------------
// ctx[b][hd] = sum_i r[b][hd>>6][i] * Wv[i][hd] + bv[hd]
// ---------------------------------------------------------------------------
__global__ __launch_bounds__(256) void ctx_kernel(
    const float* __restrict__ r, const float* __restrict__ Wv,
    const float* __restrict__ bv, float* __restrict__ ctx) {
    __shared__ float r_s[4 * DD];
    const int tid = threadIdx.x;
    const int hd = blockIdx.x * 256 + tid;
    const int b = blockIdx.y;
    const int h0 = (blockIdx.x * 256) >> 6;

    {
        const float4* src = (const float4*)(r + ((size_t)(b * HH + h0)) * DD);
        float4* dst = (float4*)r_s;
#pragma unroll
        for (int j = 0; j < 4; j++) dst[tid + j * 256] = src[tid + j * 256];
    }
    __syncthreads();

    const float* rr = r_s + ((hd >> 6) - h0) * DD;
    float acc = 0.f;
#pragma unroll 16
    for (int i = 0; i < DD; i++) acc += rr[i] * Wv[(size_t)i * DD + hd];
    ctx[(size_t)b * DD + hd] = acc + bv[hd];
}

// ---------------------------------------------------------------------------
// Launch
// ---------------------------------------------------------------------------
extern "C" void kernel_launch(void* const* d_in, const int* in_sizes, int n_in,
                              void* d_out, int out_size) {
    const float* vector = (const float*)d_in[0];
    const float* matrix = (const float*)d_in[1];
    const int*   mask   = (const int*)d_in[2];
    const float* Wq = (const float*)d_in[3];
    const float* bq = (const float*)d_in[4];
    const float* Wk = (const float*)d_in[5];
    const float* bk = (const float*)d_in[6];
    const float* Wv = (const float*)d_in[7];
    const float* bv = (const float*)d_in[8];
    const float* Wo = (const float*)d_in[9];
    const float* bo = (const float*)d_in[10];

    float* out = (float*)d_out;
    float* out_final  = out;
    float* attn_out   = out + (size_t)BB * DD;
    float* scores_out = attn_out + (size_t)BB * HH * TT;

    float *pq, *pwqt, *psb, *pr, *pctx, *ppp;
    cudaGetSymbolAddress((void**)&pq, g_q);
    cudaGetSymbolAddress((void**)&pwqt, g_wqt);
    cudaGetSymbolAddress((void**)&psb, g_sb);
    cudaGetSymbolAddress((void**)&pr, g_r);
    cudaGetSymbolAddress((void**)&pctx, g_ctx);
    cudaGetSymbolAddress((void**)&ppp, g_pp);

    cudaFuncSetAttribute(wqt_kernel,
                         cudaFuncAttributeMaxDynamicSharedMemorySize, WQT_SMEM);
    cudaFuncSetAttribute(scores_mma_kernel,
                         cudaFuncAttributeMaxDynamicSharedMemorySize, SC_SMEM);
    cudaFuncSetAttribute(rmix_kernel,
                         cudaFuncAttributeMaxDynamicSharedMemorySize, RM_SMEM);

    // q = vector @ Wq + bq (split-k)
    dim3 rpgrid(4, BB);
    rp_part_kernel<<<rpgrid, 256>>>(vector, Wq, ppp);
    rp_reduce_kernel<<<BB, 256>>>(ppp, bq, pq);

    // wq~ and sb
    dim3 wgrid(4, BB);
    wqt_kernel<<<wgrid, 256, WQT_SMEM>>>(Wk, pq, pwqt);
    sb_kernel<<<BB, 512>>>(bk, pq, psb);

    // scores = matrix @ wq~ + sb  (tf32 mma, 4-stage cp.async, 1 wave)
    dim3 sgrid(16, BB);
    scores_mma_kernel<<<sgrid, 256, SC_SMEM>>>(matrix, pwqt, psb, scores_out);

    // attn = masked softmax(scores)
    dim3 smgrid(HH, BB);
    softmax_kernel<<<smgrid, 256>>>(scores_out, mask, attn_out);

    // r = attn @ matrix (tf32 mma, 4-stage cp.async, 1 wave)
    dim3 rgrid(16, BB);
    rmix_kernel<<<rgrid, 256, RM_SMEM>>>(attn_out, matrix, pr);

    // ctx = r @ Wv + bv
    dim3 cgrid(4, BB);
    ctx_kernel<<<cgrid, 256>>>(pr, Wv, bv, pctx);

    // out = ctx @ Wo + bo (split-k)
    rp_part_kernel<<<rpgrid, 256>>>(pctx, Wo, ppp);
    rp_reduce_kernel<<<BB, 256>>>(ppp, bo, out_final);
}